// round 1
// baseline (speedup 1.0000x reference)
#include <cuda_runtime.h>
#include <cuda_bf16.h>
#include <math.h>

#define S_LEN 512
#define BSZ   128
#define EDIM  300
#define HDIM  256
#define NCLS  6
#define PDIM  256

// ---------------- scratch (device globals; no runtime allocation) ----------
__device__ float g_seq_emb[(size_t)S_LEN * BSZ * EDIM];              // 78.6 MB
__device__ float g_gx[2][(size_t)S_LEN * BSZ * 4 * HDIM];            // 536 MB
__device__ float g_h0[(size_t)BSZ * 2 * HDIM];                       // concat [fh, bh]
__device__ float g_gxc[NCLS * 3 * 2 * HDIM];                         // decoder input gates

// ---------------- helpers ---------------------------------------------------
__device__ __forceinline__ float sigmoidf_(float x) { return 1.0f / (1.0f + expf(-x)); }
// tanh via exp (avoids tanh.approx drift under fast-math builds)
__device__ __forceinline__ float tanhf_(float x) { return 1.0f - 2.0f / (expf(2.0f * x) + 1.0f); }

__device__ __forceinline__ unsigned long long pk2(float lo, float hi) {
    return ((unsigned long long)__float_as_uint(hi) << 32) | (unsigned long long)__float_as_uint(lo);
}
__device__ __forceinline__ float2 upk2(unsigned long long u) {
    float2 f; f.x = __uint_as_float((unsigned)u); f.y = __uint_as_float((unsigned)(u >> 32)); return f;
}
// packed dual-lane fp32 FMA (FFMA2) — 2x fp32 throughput on sm_103a
__device__ __forceinline__ void fma2(unsigned long long& d, unsigned long long a, unsigned long long b) {
    asm("fma.rn.f32x2 %0, %1, %2, %0;" : "+l"(d) : "l"(a), "l"(b));
}

// ---------------- kernel 1: embedding gather + tanh, time-major -------------
__global__ void embed_kernel(const int* __restrict__ seq, const float* __restrict__ embW) {
    long long idx = (long long)blockIdx.x * blockDim.x + threadIdx.x;
    const long long total = (long long)S_LEN * BSZ * EDIM;
    if (idx >= total) return;
    int e = (int)(idx % EDIM);
    int r = (int)(idx / EDIM);       // r = s*BSZ + b
    int b = r % BSZ;
    int s = r / BSZ;
    int v = seq[b * S_LEN + s];
    g_seq_emb[idx] = tanhf_(embW[(long long)v * EDIM + e]);
}

// ---------------- kernel 2: input GEMMs gx = A @ Wih^T + (bih+bhh) ----------
// A = seq_emb [65536 x 300] (dir 1 reads time-reversed rows), W = [1024 x 300]
// BM=128(=one time step), BN=128, BK=8, 256 threads, 8x8 per thread, FFMA2.
__global__ __launch_bounds__(256, 2) void gx_gemm_kernel(
    const float* __restrict__ fWih, const float* __restrict__ fbih, const float* __restrict__ fbhh,
    const float* __restrict__ bWih, const float* __restrict__ bbih, const float* __restrict__ bbhh)
{
    __shared__ float As[8][256];   // duplicated pairs: As[k][2m]=As[k][2m+1]=A(m,k)
    __shared__ float Bs[8][128];

    const int dir   = blockIdx.z;
    const int s     = blockIdx.x;                 // M tile == time step
    const int ntile = blockIdx.y;
    const float* W  = dir ? bWih : fWih;
    const float* bi = dir ? bbih : fbih;
    const float* bh = dir ? bbhh : fbhh;
    const int src_s = dir ? ((S_LEN - s) & (S_LEN - 1)) : s;
    const float* Abase = g_seq_emb + (size_t)src_s * BSZ * EDIM;

    const int t   = threadIdx.x;
    const int lm  = t >> 1;            // row within tile for loads
    const int lkq = (t & 1) * 4;       // k quad
    const int tm  = t >> 4;            // 0..15 compute row group
    const int tn  = t & 15;            // 0..15 compute col group

    unsigned long long acc2[8][4];
#pragma unroll
    for (int i = 0; i < 8; i++)
#pragma unroll
        for (int j = 0; j < 4; j++) acc2[i][j] = 0ULL;

    const int NK = (EDIM + 7) / 8;     // 38
    for (int kt = 0; kt < NK; kt++) {
        const int k0 = kt * 8;
        float4 av = make_float4(0.f, 0.f, 0.f, 0.f);
        float4 bv = make_float4(0.f, 0.f, 0.f, 0.f);
        if (k0 + lkq + 3 < EDIM) {     // EDIM%4==0 -> whole quad valid or whole OOB
            av = *(const float4*)(Abase + (size_t)lm * EDIM + k0 + lkq);
            bv = *(const float4*)(W + (size_t)(ntile * 128 + lm) * EDIM + k0 + lkq);
        }
        __syncthreads();
        As[lkq + 0][2 * lm] = av.x; As[lkq + 0][2 * lm + 1] = av.x;
        As[lkq + 1][2 * lm] = av.y; As[lkq + 1][2 * lm + 1] = av.y;
        As[lkq + 2][2 * lm] = av.z; As[lkq + 2][2 * lm + 1] = av.z;
        As[lkq + 3][2 * lm] = av.w; As[lkq + 3][2 * lm + 1] = av.w;
        Bs[lkq + 0][lm] = bv.x; Bs[lkq + 1][lm] = bv.y;
        Bs[lkq + 2][lm] = bv.z; Bs[lkq + 3][lm] = bv.w;
        __syncthreads();
#pragma unroll
        for (int k = 0; k < 8; k++) {
            const unsigned long long* ap = (const unsigned long long*)&As[k][(tm * 8) * 2];
            const unsigned long long* bp = (const unsigned long long*)&Bs[k][tn * 8];
            unsigned long long bb0 = bp[0], bb1 = bp[1], bb2 = bp[2], bb3 = bp[3];
#pragma unroll
            for (int i = 0; i < 8; i++) {
                unsigned long long a2 = ap[i];   // (a,a)
                fma2(acc2[i][0], a2, bb0);
                fma2(acc2[i][1], a2, bb1);
                fma2(acc2[i][2], a2, bb2);
                fma2(acc2[i][3], a2, bb3);
            }
        }
    }
    // epilogue: add (bih + bhh), write gx[dir][(s*128+m)*1024 + n]
    const int ncol0 = ntile * 128 + tn * 8;
    float bias[8];
#pragma unroll
    for (int j = 0; j < 8; j++) bias[j] = bi[ncol0 + j] + bh[ncol0 + j];
#pragma unroll
    for (int i = 0; i < 8; i++) {
        const int ro = s * 128 + tm * 8 + i;
        float* orow = g_gx[dir] + (size_t)ro * 1024 + ncol0;
#pragma unroll
        for (int j = 0; j < 4; j++) {
            float2 v = upk2(acc2[i][j]);
            orow[2 * j]     = v.x + bias[2 * j];
            orow[2 * j + 1] = v.y + bias[2 * j + 1];
        }
    }
}

// ---------------- kernel 3: LSTM recurrence (both directions) ---------------
// Batch elements are independent -> each block owns G=4 batch rows, loops all
// 512 steps internally with only __syncthreads. Thread u owns hidden unit u
// (gate rows u, 256+u, 512+u, 768+u of Whh[1024][256]). c stays in registers.
__global__ __launch_bounds__(256) void lstm_kernel(const float* __restrict__ fWhh,
                                                   const float* __restrict__ bWhh)
{
    const int G = 4;
    const int dir = blockIdx.y;
    const int b0  = blockIdx.x * G;
    const float* W = dir ? bWhh : fWhh;
    const float* gx = g_gx[dir];
    const int u = threadIdx.x;

    __shared__ float hbuf[2][G][HDIM];
#pragma unroll
    for (int b = 0; b < G; b++) hbuf[0][b][u] = 0.0f;
    float c[G];
#pragma unroll
    for (int b = 0; b < G; b++) c[b] = 0.0f;
    __syncthreads();

    const ulonglong2* wr[4];
#pragma unroll
    for (int g = 0; g < 4; g++) wr[g] = (const ulonglong2*)(W + (size_t)(g * HDIM + u) * HDIM);

    for (int s = 0; s < S_LEN; s++) {
        const int cur = s & 1, nxt = cur ^ 1;
        const float* gxs = gx + ((size_t)s * BSZ + b0) * 1024;
        float gxv[4][G];
#pragma unroll
        for (int g = 0; g < 4; g++)
#pragma unroll
            for (int b = 0; b < G; b++) gxv[g][b] = gxs[b * 1024 + g * HDIM + u];

        unsigned long long acc2[4][G];
#pragma unroll
        for (int g = 0; g < 4; g++)
#pragma unroll
            for (int b = 0; b < G; b++) acc2[g][b] = 0ULL;

        const unsigned long long* hp[G];
#pragma unroll
        for (int b = 0; b < G; b++) hp[b] = (const unsigned long long*)hbuf[cur][b];

#pragma unroll 8
        for (int k4 = 0; k4 < HDIM / 4; k4++) {
            unsigned long long h2[G][2];
#pragma unroll
            for (int b = 0; b < G; b++) { h2[b][0] = hp[b][2 * k4]; h2[b][1] = hp[b][2 * k4 + 1]; }
#pragma unroll
            for (int g = 0; g < 4; g++) {
                ulonglong2 w = wr[g][k4];
#pragma unroll
                for (int b = 0; b < G; b++) {
                    fma2(acc2[g][b], w.x, h2[b][0]);
                    fma2(acc2[g][b], w.y, h2[b][1]);
                }
            }
        }
#pragma unroll
        for (int b = 0; b < G; b++) {
            float2 t0 = upk2(acc2[0][b]); float gi = gxv[0][b] + t0.x + t0.y;
            float2 t1 = upk2(acc2[1][b]); float gf = gxv[1][b] + t1.x + t1.y;
            float2 t2 = upk2(acc2[2][b]); float gg = gxv[2][b] + t2.x + t2.y;
            float2 t3 = upk2(acc2[3][b]); float go = gxv[3][b] + t3.x + t3.y;
            float cc = sigmoidf_(gf) * c[b] + sigmoidf_(gi) * tanhf_(gg);
            c[b] = cc;
            hbuf[nxt][b][u] = sigmoidf_(go) * tanhf_(cc);
        }
        __syncthreads();
    }
    // after s=511 (odd), final h is in hbuf[0]
#pragma unroll
    for (int b = 0; b < G; b++)
        g_h0[(size_t)(b0 + b) * (2 * HDIM) + dir * HDIM + u] = hbuf[0][b][u];
}

// ---------------- kernel 4: decoder input gates (per class, batch-invariant)-
__global__ void dec_prep_kernel(const int* __restrict__ classes, const float* __restrict__ ecW,
                                const float* __restrict__ dWih, const float* __restrict__ dbih)
{
    __shared__ float ce[EDIM];
    const int c = blockIdx.x;
    const int cls = classes[c];
    for (int e = threadIdx.x; e < EDIM; e += blockDim.x)
        ce[e] = tanhf_(ecW[(size_t)cls * EDIM + e]);
    __syncthreads();
    for (int j = threadIdx.x; j < 3 * 2 * HDIM; j += blockDim.x) {
        float acc = dbih[j];
        const float* w = dWih + (size_t)j * EDIM;
        for (int k = 0; k < EDIM; k++) acc += w[k] * ce[k];
        g_gxc[c * 1536 + j] = acc;
    }
}

// ---------------- kernel 5: decoder GRU + proj + cls + log_softmax ----------
// Gd=2 batch rows per block, 512 threads (thread u owns decoder unit u).
__global__ __launch_bounds__(512) void dec_kernel(
    const float* __restrict__ dWhh, const float* __restrict__ dbhh,
    const float* __restrict__ projW, const float* __restrict__ projB,
    const float* __restrict__ clsW, const float* __restrict__ clsB,
    float* __restrict__ out)
{
    const int Gd = 2;
    const int H2 = 2 * HDIM;     // 512
    const int b0 = blockIdx.x * Gd;
    const int u  = threadIdx.x;

    __shared__ float hb[2][Gd][512];
    __shared__ float projs[Gd][PDIM];
    __shared__ float lgs[Gd][2];

#pragma unroll
    for (int b = 0; b < Gd; b++) hb[0][b][u] = g_h0[(size_t)(b0 + b) * H2 + u];
    __syncthreads();

    const ulonglong2* wr[3];
    float bh[3];
#pragma unroll
    for (int g = 0; g < 3; g++) {
        wr[g] = (const ulonglong2*)(dWhh + (size_t)(g * H2 + u) * H2);
        bh[g] = dbhh[g * H2 + u];
    }

    for (int c = 0; c < NCLS; c++) {
        const int cur = c & 1, nxt = cur ^ 1;
        unsigned long long acc2[3][Gd];
#pragma unroll
        for (int g = 0; g < 3; g++)
#pragma unroll
            for (int b = 0; b < Gd; b++) acc2[g][b] = 0ULL;
        const unsigned long long* hp[Gd];
#pragma unroll
        for (int b = 0; b < Gd; b++) hp[b] = (const unsigned long long*)hb[cur][b];

#pragma unroll 8
        for (int k4 = 0; k4 < H2 / 4; k4++) {
            unsigned long long h2[Gd][2];
#pragma unroll
            for (int b = 0; b < Gd; b++) { h2[b][0] = hp[b][2 * k4]; h2[b][1] = hp[b][2 * k4 + 1]; }
#pragma unroll
            for (int g = 0; g < 3; g++) {
                ulonglong2 w = wr[g][k4];
#pragma unroll
                for (int b = 0; b < Gd; b++) {
                    fma2(acc2[g][b], w.x, h2[b][0]);
                    fma2(acc2[g][b], w.y, h2[b][1]);
                }
            }
        }
        const float gxr = g_gxc[c * 1536 + u];
        const float gxz = g_gxc[c * 1536 + H2 + u];
        const float gxn = g_gxc[c * 1536 + 2 * H2 + u];
#pragma unroll
        for (int b = 0; b < Gd; b++) {
            float2 t;
            t = upk2(acc2[0][b]); float ghr = t.x + t.y + bh[0];
            t = upk2(acc2[1][b]); float ghz = t.x + t.y + bh[1];
            t = upk2(acc2[2][b]); float ghn = t.x + t.y + bh[2];
            float r = sigmoidf_(gxr + ghr);
            float z = sigmoidf_(gxz + ghz);
            float n = tanhf_(gxn + r * ghn);
            float hold = hb[cur][b][u];
            hb[nxt][b][u] = tanhf_((1.0f - z) * n + z * hold);
        }
        __syncthreads();

        // projection: thread u -> (b = u>>8, p = u&255), dot over 512
        {
            const int b = u >> 8, p = u & 255;
            const float4* w = (const float4*)(projW + (size_t)p * H2);
            const float4* hv = (const float4*)hb[nxt][b];
            float acc = projB[p];
            for (int k4 = 0; k4 < H2 / 4; k4++) {
                float4 wv = w[k4], hvv = hv[k4];
                acc += wv.x * hvv.x + wv.y * hvv.y + wv.z * hvv.z + wv.w * hvv.w;
            }
            projs[b][p] = acc;
        }
        __syncthreads();

        // class logits: warp w handles (b = w>>1, cls = w&1)
        const int wid = u >> 5, lid = u & 31;
        if (wid < Gd * 2) {
            const int b = wid >> 1, cl = wid & 1;
            float acc = 0.0f;
            for (int k = lid; k < PDIM; k += 32) acc += clsW[cl * PDIM + k] * projs[b][k];
#pragma unroll
            for (int o = 16; o > 0; o >>= 1) acc += __shfl_down_sync(0xffffffffu, acc, o);
            if (lid == 0) lgs[b][cl] = acc + clsB[cl];
        }
        __syncthreads();
        if (u < Gd) {
            const int b = u;
            float l0 = lgs[b][0], l1 = lgs[b][1];
            float m = fmaxf(l0, l1);
            float lse = m + logf(expf(l0 - m) + expf(l1 - m));
            out[(size_t)c * BSZ * 2 + (b0 + b) * 2 + 0] = l0 - lse;
            out[(size_t)c * BSZ * 2 + (b0 + b) * 2 + 1] = l1 - lse;
        }
        __syncthreads();
    }
}

// ---------------- launch -----------------------------------------------------
extern "C" void kernel_launch(void* const* d_in, const int* in_sizes, int n_in,
                              void* d_out, int out_size)
{
    const int*   seq     = (const int*)d_in[0];
    const int*   classes = (const int*)d_in[1];
    const float* embW    = (const float*)d_in[2];
    const float* ecW     = (const float*)d_in[3];
    const float* fWih    = (const float*)d_in[4];
    const float* fWhh    = (const float*)d_in[5];
    const float* fbih    = (const float*)d_in[6];
    const float* fbhh    = (const float*)d_in[7];
    const float* bWih    = (const float*)d_in[8];
    const float* bWhh    = (const float*)d_in[9];
    const float* bbih    = (const float*)d_in[10];
    const float* bbhh    = (const float*)d_in[11];
    const float* dWih    = (const float*)d_in[12];
    const float* dWhh    = (const float*)d_in[13];
    const float* dbih    = (const float*)d_in[14];
    const float* dbhh    = (const float*)d_in[15];
    const float* projW   = (const float*)d_in[16];
    const float* projB   = (const float*)d_in[17];
    const float* clsW    = (const float*)d_in[18];
    const float* clsB    = (const float*)d_in[19];
    float* out = (float*)d_out;

    {   // 1. embeddings (time-major) + tanh
        long long total = (long long)S_LEN * BSZ * EDIM;
        int blocks = (int)((total + 255) / 256);
        embed_kernel<<<blocks, 256>>>(seq, embW);
    }
    {   // 2. input-gate GEMMs for both directions (biases folded)
        dim3 grid(S_LEN, 1024 / 128, 2);
        gx_gemm_kernel<<<grid, 256>>>(fWih, fbih, fbhh, bWih, bbih, bbhh);
    }
    {   // 3. bidirectional LSTM recurrence (persistent per-block loops)
        dim3 grid(BSZ / 4, 2);
        lstm_kernel<<<grid, 256>>>(fWhh, bWhh);
    }
    {   // 4. decoder input gates per class
        dec_prep_kernel<<<NCLS, 256>>>(classes, ecW, dWih, dbih);
    }
    {   // 5. decoder GRU + projection + classifier + log_softmax
        dec_kernel<<<BSZ / 2, 512>>>(dWhh, dbhh, projW, projB, clsW, clsB, out);
    }
    (void)in_sizes; (void)n_in; (void)out_size;
}

// round 2
// speedup vs baseline: 1.0064x; 1.0064x over previous
#include <cuda_runtime.h>
#include <cuda_bf16.h>
#include <math.h>

#define S_LEN 512
#define BSZ   128
#define EDIM  300
#define HDIM  256
#define NCLS  6
#define PDIM  256

// ---------------- scratch (device globals; no runtime allocation) ----------
__device__ float g_seq_emb[(size_t)S_LEN * BSZ * EDIM];              // 78.6 MB
__device__ float g_gx[2][(size_t)S_LEN * BSZ * 4 * HDIM];            // 536 MB
__device__ float g_h0[(size_t)BSZ * 2 * HDIM];                       // concat [fh, bh]
__device__ float g_gxc[NCLS * 3 * 2 * HDIM];                         // decoder input gates

// ---------------- helpers ---------------------------------------------------
__device__ __forceinline__ float sigmoidf_(float x) { return 1.0f / (1.0f + expf(-x)); }
__device__ __forceinline__ float tanhf_(float x) { return 1.0f - 2.0f / (expf(2.0f * x) + 1.0f); }

__device__ __forceinline__ float2 upk2(unsigned long long u) {
    float2 f; f.x = __uint_as_float((unsigned)u); f.y = __uint_as_float((unsigned)(u >> 32)); return f;
}
// packed dual-lane fp32 FMA (FFMA2) — 2x fp32 throughput on sm_103a
__device__ __forceinline__ void fma2(unsigned long long& d, unsigned long long a, unsigned long long b) {
    asm("fma.rn.f32x2 %0, %1, %2, %0;" : "+l"(d) : "l"(a), "l"(b));
}

// ---------------- kernel 1: embedding gather + tanh, time-major -------------
__global__ void embed_kernel(const int* __restrict__ seq, const float* __restrict__ embW) {
    long long idx = (long long)blockIdx.x * blockDim.x + threadIdx.x;
    const long long total = (long long)S_LEN * BSZ * EDIM;
    if (idx >= total) return;
    int e = (int)(idx % EDIM);
    int r = (int)(idx / EDIM);       // r = s*BSZ + b
    int b = r % BSZ;
    int s = r / BSZ;
    int v = seq[b * S_LEN + s];
    g_seq_emb[idx] = tanhf_(embW[(long long)v * EDIM + e]);
}

// ---------------- kernel 2: input GEMMs gx = A @ Wih^T + (bih+bhh) ----------
// A = seq_emb [65536 x 300] (dir 1 reads time-reversed rows), W = [1024 x 300]
// BM=128(=one time step), BN=128, BK=16, 256 threads, 8x8 per thread, FFMA2.
// NOTE: no minBlocksPerMultiprocessor cap -> let ptxas keep everything in regs.
__global__ __launch_bounds__(256) void gx_gemm_kernel(
    const float* __restrict__ fWih, const float* __restrict__ fbih, const float* __restrict__ fbhh,
    const float* __restrict__ bWih, const float* __restrict__ bbih, const float* __restrict__ bbhh)
{
    __shared__ float As[16][256];   // duplicated pairs: As[k][2m]=As[k][2m+1]=A(m,k)
    __shared__ float Bs[16][128];

    const int dir   = blockIdx.z;
    const int s     = blockIdx.x;                 // M tile == time step
    const int ntile = blockIdx.y;
    const float* W  = dir ? bWih : fWih;
    const float* bi = dir ? bbih : fbih;
    const float* bh = dir ? bbhh : fbhh;
    const int src_s = dir ? ((S_LEN - s) & (S_LEN - 1)) : s;
    const float* Abase = g_seq_emb + (size_t)src_s * BSZ * EDIM;

    const int t   = threadIdx.x;
    const int lr  = t & 127;           // row within tile for loads
    const int lqp = t >> 7;            // quad-pair selector (0/1)
    const int tm  = t >> 4;            // 0..15 compute row group
    const int tn  = t & 15;            // 0..15 compute col group

    unsigned long long acc2[8][4];
#pragma unroll
    for (int i = 0; i < 8; i++)
#pragma unroll
        for (int j = 0; j < 4; j++) acc2[i][j] = 0ULL;

    const int NK = (EDIM + 15) / 16;   // 19
    for (int kt = 0; kt < NK; kt++) {
        float4 av[2], bv[2];
#pragma unroll
        for (int q = 0; q < 2; q++) {
            const int kk = kt * 16 + (lqp * 2 + q) * 4;
            av[q] = make_float4(0.f, 0.f, 0.f, 0.f);
            bv[q] = make_float4(0.f, 0.f, 0.f, 0.f);
            if (kk + 3 < EDIM) {       // EDIM%4==0 -> quad fully valid or fully OOB
                av[q] = *(const float4*)(Abase + (size_t)lr * EDIM + kk);
                bv[q] = *(const float4*)(W + (size_t)(ntile * 128 + lr) * EDIM + kk);
            }
        }
        __syncthreads();
#pragma unroll
        for (int q = 0; q < 2; q++) {
            const int kb = (lqp * 2 + q) * 4;
            As[kb + 0][2 * lr] = av[q].x; As[kb + 0][2 * lr + 1] = av[q].x;
            As[kb + 1][2 * lr] = av[q].y; As[kb + 1][2 * lr + 1] = av[q].y;
            As[kb + 2][2 * lr] = av[q].z; As[kb + 2][2 * lr + 1] = av[q].z;
            As[kb + 3][2 * lr] = av[q].w; As[kb + 3][2 * lr + 1] = av[q].w;
            Bs[kb + 0][lr] = bv[q].x; Bs[kb + 1][lr] = bv[q].y;
            Bs[kb + 2][lr] = bv[q].z; Bs[kb + 3][lr] = bv[q].w;
        }
        __syncthreads();
#pragma unroll
        for (int k = 0; k < 16; k++) {
            const unsigned long long* ap = (const unsigned long long*)&As[k][0] + tm * 8;
            const unsigned long long* bp = (const unsigned long long*)&Bs[k][0] + tn * 4;
            unsigned long long bb0 = bp[0], bb1 = bp[1], bb2 = bp[2], bb3 = bp[3];
#pragma unroll
            for (int i = 0; i < 8; i++) {
                unsigned long long a2 = ap[i];   // (a,a)
                fma2(acc2[i][0], a2, bb0);
                fma2(acc2[i][1], a2, bb1);
                fma2(acc2[i][2], a2, bb2);
                fma2(acc2[i][3], a2, bb3);
            }
        }
    }
    // epilogue: add (bih + bhh), write gx[dir][(s*128+m)*1024 + n]
    const int ncol0 = ntile * 128 + tn * 8;
    float bias[8];
#pragma unroll
    for (int j = 0; j < 8; j++) bias[j] = bi[ncol0 + j] + bh[ncol0 + j];
#pragma unroll
    for (int i = 0; i < 8; i++) {
        const int ro = s * 128 + tm * 8 + i;
        float* orow = g_gx[dir] + (size_t)ro * 1024 + ncol0;
#pragma unroll
        for (int j = 0; j < 4; j++) {
            float2 v = upk2(acc2[i][j]);
            orow[2 * j]     = v.x + bias[2 * j];
            orow[2 * j + 1] = v.y + bias[2 * j + 1];
        }
    }
}

// ---------------- kernel 3: LSTM recurrence (both directions) ---------------
// Batch elements independent -> block owns G=4 batch rows, loops 512 steps with
// only __syncthreads. Thread u owns hidden unit u (gate rows u, 256+u, 512+u,
// 768+u of Whh[1024][256]); c stays in registers. Unroll 4 to bound live regs.
__global__ __launch_bounds__(256) void lstm_kernel(const float* __restrict__ fWhh,
                                                   const float* __restrict__ bWhh)
{
    const int G = 4;
    const int dir = blockIdx.y;
    const int b0  = blockIdx.x * G;
    const float* W = dir ? bWhh : fWhh;
    const float* gx = g_gx[dir];
    const int u = threadIdx.x;

    __shared__ float hbuf[2][G][HDIM];
#pragma unroll
    for (int b = 0; b < G; b++) hbuf[0][b][u] = 0.0f;
    float c[G];
#pragma unroll
    for (int b = 0; b < G; b++) c[b] = 0.0f;
    __syncthreads();

    const ulonglong2* wr[4];
#pragma unroll
    for (int g = 0; g < 4; g++) wr[g] = (const ulonglong2*)(W + (size_t)(g * HDIM + u) * HDIM);

    for (int s = 0; s < S_LEN; s++) {
        const int cur = s & 1, nxt = cur ^ 1;
        const float* gxs = gx + ((size_t)s * BSZ + b0) * 1024;
        float gxv[4][G];
#pragma unroll
        for (int g = 0; g < 4; g++)
#pragma unroll
            for (int b = 0; b < G; b++) gxv[g][b] = gxs[b * 1024 + g * HDIM + u];

        unsigned long long acc2[4][G];
#pragma unroll
        for (int g = 0; g < 4; g++)
#pragma unroll
            for (int b = 0; b < G; b++) acc2[g][b] = 0ULL;

        const unsigned long long* hp[G];
#pragma unroll
        for (int b = 0; b < G; b++) hp[b] = (const unsigned long long*)hbuf[cur][b];

#pragma unroll 4
        for (int k4 = 0; k4 < HDIM / 4; k4++) {
            unsigned long long h2[G][2];
#pragma unroll
            for (int b = 0; b < G; b++) { h2[b][0] = hp[b][2 * k4]; h2[b][1] = hp[b][2 * k4 + 1]; }
#pragma unroll
            for (int g = 0; g < 4; g++) {
                ulonglong2 w = wr[g][k4];
#pragma unroll
                for (int b = 0; b < G; b++) {
                    fma2(acc2[g][b], w.x, h2[b][0]);
                    fma2(acc2[g][b], w.y, h2[b][1]);
                }
            }
        }
#pragma unroll
        for (int b = 0; b < G; b++) {
            float2 t0 = upk2(acc2[0][b]); float gi = gxv[0][b] + t0.x + t0.y;
            float2 t1 = upk2(acc2[1][b]); float gf = gxv[1][b] + t1.x + t1.y;
            float2 t2 = upk2(acc2[2][b]); float gg = gxv[2][b] + t2.x + t2.y;
            float2 t3 = upk2(acc2[3][b]); float go = gxv[3][b] + t3.x + t3.y;
            float cc = sigmoidf_(gf) * c[b] + sigmoidf_(gi) * tanhf_(gg);
            c[b] = cc;
            hbuf[nxt][b][u] = sigmoidf_(go) * tanhf_(cc);
        }
        __syncthreads();
    }
    // after s=511 (odd), final h is in hbuf[0]
#pragma unroll
    for (int b = 0; b < G; b++)
        g_h0[(size_t)(b0 + b) * (2 * HDIM) + dir * HDIM + u] = hbuf[0][b][u];
}

// ---------------- kernel 4: decoder input gates (per class, batch-invariant)-
// grid (NCLS, 6) x 256 threads: one output per thread, float4 weight reads.
__global__ __launch_bounds__(256) void dec_prep_kernel(
    const int* __restrict__ classes, const float* __restrict__ ecW,
    const float* __restrict__ dWih, const float* __restrict__ dbih)
{
    __shared__ float ce[EDIM];
    const int c = blockIdx.x;
    const int cls = classes[c];
    for (int e = threadIdx.x; e < EDIM; e += blockDim.x)
        ce[e] = tanhf_(ecW[(size_t)cls * EDIM + e]);
    __syncthreads();
    const int j = blockIdx.y * 256 + threadIdx.x;    // 6*256 = 1536 outputs
    float acc = dbih[j];
    const float4* w = (const float4*)(dWih + (size_t)j * EDIM);
#pragma unroll 5
    for (int k = 0; k < EDIM / 4; k++) {
        float4 wv = w[k];
        acc += wv.x * ce[4 * k] + wv.y * ce[4 * k + 1] + wv.z * ce[4 * k + 2] + wv.w * ce[4 * k + 3];
    }
    g_gxc[c * 1536 + j] = acc;
}

// ---------------- kernel 5: decoder GRU + proj + cls + log_softmax ----------
__global__ __launch_bounds__(512) void dec_kernel(
    const float* __restrict__ dWhh, const float* __restrict__ dbhh,
    const float* __restrict__ projW, const float* __restrict__ projB,
    const float* __restrict__ clsW, const float* __restrict__ clsB,
    float* __restrict__ out)
{
    const int Gd = 2;
    const int H2 = 2 * HDIM;     // 512
    const int b0 = blockIdx.x * Gd;
    const int u  = threadIdx.x;

    __shared__ float hb[2][Gd][512];
    __shared__ float projs[Gd][PDIM];
    __shared__ float lgs[Gd][2];

#pragma unroll
    for (int b = 0; b < Gd; b++) hb[0][b][u] = g_h0[(size_t)(b0 + b) * H2 + u];
    __syncthreads();

    const ulonglong2* wr[3];
    float bh[3];
#pragma unroll
    for (int g = 0; g < 3; g++) {
        wr[g] = (const ulonglong2*)(dWhh + (size_t)(g * H2 + u) * H2);
        bh[g] = dbhh[g * H2 + u];
    }

    for (int c = 0; c < NCLS; c++) {
        const int cur = c & 1, nxt = cur ^ 1;
        unsigned long long acc2[3][Gd];
#pragma unroll
        for (int g = 0; g < 3; g++)
#pragma unroll
            for (int b = 0; b < Gd; b++) acc2[g][b] = 0ULL;
        const unsigned long long* hp[Gd];
#pragma unroll
        for (int b = 0; b < Gd; b++) hp[b] = (const unsigned long long*)hb[cur][b];

#pragma unroll 4
        for (int k4 = 0; k4 < H2 / 4; k4++) {
            unsigned long long h2[Gd][2];
#pragma unroll
            for (int b = 0; b < Gd; b++) { h2[b][0] = hp[b][2 * k4]; h2[b][1] = hp[b][2 * k4 + 1]; }
#pragma unroll
            for (int g = 0; g < 3; g++) {
                ulonglong2 w = wr[g][k4];
#pragma unroll
                for (int b = 0; b < Gd; b++) {
                    fma2(acc2[g][b], w.x, h2[b][0]);
                    fma2(acc2[g][b], w.y, h2[b][1]);
                }
            }
        }
        const float gxr = g_gxc[c * 1536 + u];
        const float gxz = g_gxc[c * 1536 + H2 + u];
        const float gxn = g_gxc[c * 1536 + 2 * H2 + u];
#pragma unroll
        for (int b = 0; b < Gd; b++) {
            float2 t;
            t = upk2(acc2[0][b]); float ghr = t.x + t.y + bh[0];
            t = upk2(acc2[1][b]); float ghz = t.x + t.y + bh[1];
            t = upk2(acc2[2][b]); float ghn = t.x + t.y + bh[2];
            float r = sigmoidf_(gxr + ghr);
            float z = sigmoidf_(gxz + ghz);
            float n = tanhf_(gxn + r * ghn);
            float hold = hb[cur][b][u];
            hb[nxt][b][u] = tanhf_((1.0f - z) * n + z * hold);
        }
        __syncthreads();

        // projection: thread u -> (b = u>>8, p = u&255), dot over 512
        {
            const int b = u >> 8, p = u & 255;
            const float4* w = (const float4*)(projW + (size_t)p * H2);
            const float4* hv = (const float4*)hb[nxt][b];
            float acc = projB[p];
            for (int k4 = 0; k4 < H2 / 4; k4++) {
                float4 wv = w[k4], hvv = hv[k4];
                acc += wv.x * hvv.x + wv.y * hvv.y + wv.z * hvv.z + wv.w * hvv.w;
            }
            projs[b][p] = acc;
        }
        __syncthreads();

        // class logits: warp w handles (b = w>>1, cls = w&1)
        const int wid = u >> 5, lid = u & 31;
        if (wid < Gd * 2) {
            const int b = wid >> 1, cl = wid & 1;
            float acc = 0.0f;
            for (int k = lid; k < PDIM; k += 32) acc += clsW[cl * PDIM + k] * projs[b][k];
#pragma unroll
            for (int o = 16; o > 0; o >>= 1) acc += __shfl_down_sync(0xffffffffu, acc, o);
            if (lid == 0) lgs[b][cl] = acc + clsB[cl];
        }
        __syncthreads();
        if (u < Gd) {
            const int b = u;
            float l0 = lgs[b][0], l1 = lgs[b][1];
            float m = fmaxf(l0, l1);
            float lse = m + logf(expf(l0 - m) + expf(l1 - m));
            out[(size_t)c * BSZ * 2 + (b0 + b) * 2 + 0] = l0 - lse;
            out[(size_t)c * BSZ * 2 + (b0 + b) * 2 + 1] = l1 - lse;
        }
        __syncthreads();
    }
}

// ---------------- launch -----------------------------------------------------
extern "C" void kernel_launch(void* const* d_in, const int* in_sizes, int n_in,
                              void* d_out, int out_size)
{
    const int*   seq     = (const int*)d_in[0];
    const int*   classes = (const int*)d_in[1];
    const float* embW    = (const float*)d_in[2];
    const float* ecW     = (const float*)d_in[3];
    const float* fWih    = (const float*)d_in[4];
    const float* fWhh    = (const float*)d_in[5];
    const float* fbih    = (const float*)d_in[6];
    const float* fbhh    = (const float*)d_in[7];
    const float* bWih    = (const float*)d_in[8];
    const float* bWhh    = (const float*)d_in[9];
    const float* bbih    = (const float*)d_in[10];
    const float* bbhh    = (const float*)d_in[11];
    const float* dWih    = (const float*)d_in[12];
    const float* dWhh    = (const float*)d_in[13];
    const float* dbih    = (const float*)d_in[14];
    const float* dbhh    = (const float*)d_in[15];
    const float* projW   = (const float*)d_in[16];
    const float* projB   = (const float*)d_in[17];
    const float* clsW    = (const float*)d_in[18];
    const float* clsB    = (const float*)d_in[19];
    float* out = (float*)d_out;

    {   // 1. embeddings (time-major) + tanh
        long long total = (long long)S_LEN * BSZ * EDIM;
        int blocks = (int)((total + 255) / 256);
        embed_kernel<<<blocks, 256>>>(seq, embW);
    }
    {   // 2. input-gate GEMMs for both directions (biases folded)
        dim3 grid(S_LEN, 1024 / 128, 2);
        gx_gemm_kernel<<<grid, 256>>>(fWih, fbih, fbhh, bWih, bbih, bbhh);
    }
    {   // 3. bidirectional LSTM recurrence (persistent per-block loops)
        dim3 grid(BSZ / 4, 2);
        lstm_kernel<<<grid, 256>>>(fWhh, bWhh);
    }
    {   // 4. decoder input gates per class
        dim3 grid(NCLS, 6);
        dec_prep_kernel<<<grid, 256>>>(classes, ecW, dWih, dbih);
    }
    {   // 5. decoder GRU + projection + classifier + log_softmax
        dec_kernel<<<BSZ / 2, 512>>>(dWhh, dbhh, projW, projB, clsW, clsB, out);
    }
    (void)in_sizes; (void)n_in; (void)out_size;
}

// round 3
// speedup vs baseline: 1.8263x; 1.8147x over previous
#include <cuda_runtime.h>
#include <cuda_bf16.h>
#include <math.h>

#define S_LEN 512
#define BSZ   128
#define EDIM  300
#define HDIM  256
#define NCLS  6
#define PDIM  256

// ---------------- scratch (device globals; no runtime allocation) ----------
__device__ float g_seq_emb[(size_t)S_LEN * BSZ * EDIM];              // 78.6 MB
__device__ float g_gx[2][(size_t)S_LEN * BSZ * 4 * HDIM];            // 536 MB
__device__ float g_h0[(size_t)BSZ * 2 * HDIM];                       // concat [fh, bh]
__device__ float g_gxc[NCLS * 3 * 2 * HDIM];                         // decoder input gates
// transposed weights (filled once per launch; coalesced access in recurrences)
__device__ float g_Wt4[2][HDIM][HDIM][4];                            // [dir][k][u][gate i,f,g,o]  2 MB
__device__ float g_dWt4[2 * HDIM][2 * HDIM][4];                      // [k][u][gate r,z,n,pad]     4 MB

// ---------------- helpers ---------------------------------------------------
__device__ __forceinline__ float sigmoidf_(float x) { return 1.0f / (1.0f + expf(-x)); }
__device__ __forceinline__ float tanhf_(float x) { return 1.0f - 2.0f / (expf(2.0f * x) + 1.0f); }

__device__ __forceinline__ unsigned long long pk2(float lo, float hi) {
    return ((unsigned long long)__float_as_uint(hi) << 32) | (unsigned long long)__float_as_uint(lo);
}
__device__ __forceinline__ float2 upk2(unsigned long long u) {
    float2 f; f.x = __uint_as_float((unsigned)u); f.y = __uint_as_float((unsigned)(u >> 32)); return f;
}
// packed dual-lane fp32 FMA (FFMA2) — 2x fp32 throughput on sm_103a
__device__ __forceinline__ void fma2(unsigned long long& d, unsigned long long a, unsigned long long b) {
    asm("fma.rn.f32x2 %0, %1, %2, %0;" : "+l"(d) : "l"(a), "l"(b));
}

// ---------------- kernel 0a: transpose LSTM Whh -----------------------------
// Wt4[dir][k][u][g] = Whh[dir][g*256+u][k]; 32x32 smem tile transpose.
__global__ __launch_bounds__(1024) void transpose_lstm_w(const float* __restrict__ fWhh,
                                                         const float* __restrict__ bWhh)
{
    __shared__ float t[32][33];
    const int dir = blockIdx.z >> 2;
    const int g   = blockIdx.z & 3;
    const int k0  = blockIdx.x * 32;
    const int u0  = blockIdx.y * 32;
    const int tx = threadIdx.x & 31, ty = threadIdx.x >> 5;
    const float* W = dir ? bWhh : fWhh;
    t[ty][tx] = W[(size_t)(g * HDIM + u0 + ty) * HDIM + k0 + tx];   // coalesced read
    __syncthreads();
    g_Wt4[dir][k0 + ty][u0 + tx][g] = t[tx][ty];
}

// ---------------- kernel 0b: transpose decoder Whh ---------------------------
// dWt4[k][u][g] = dWhh[g*512+u][k] for g in {0,1,2}; [3] stays zero (bss).
__global__ __launch_bounds__(1024) void transpose_dec_w(const float* __restrict__ dWhh)
{
    __shared__ float t[32][33];
    const int g  = blockIdx.z;
    const int k0 = blockIdx.x * 32;
    const int u0 = blockIdx.y * 32;
    const int tx = threadIdx.x & 31, ty = threadIdx.x >> 5;
    t[ty][tx] = dWhh[(size_t)(g * 2 * HDIM + u0 + ty) * (2 * HDIM) + k0 + tx];
    __syncthreads();
    g_dWt4[k0 + ty][u0 + tx][g] = t[tx][ty];
}

// ---------------- kernel 1: embedding gather + tanh, time-major -------------
__global__ void embed_kernel(const int* __restrict__ seq, const float* __restrict__ embW) {
    long long idx = (long long)blockIdx.x * blockDim.x + threadIdx.x;
    const long long total = (long long)S_LEN * BSZ * EDIM;
    if (idx >= total) return;
    int e = (int)(idx % EDIM);
    int r = (int)(idx / EDIM);       // r = s*BSZ + b
    int b = r % BSZ;
    int s = r / BSZ;
    int v = seq[b * S_LEN + s];
    g_seq_emb[idx] = tanhf_(embW[(long long)v * EDIM + e]);
}

// ---------------- kernel 2: input GEMMs gx = A @ Wih^T + (bih+bhh) ----------
// BM=128(=one time step), BN=128, BK=16, 256 threads, 8x8 per thread, FFMA2.
__global__ __launch_bounds__(256) void gx_gemm_kernel(
    const float* __restrict__ fWih, const float* __restrict__ fbih, const float* __restrict__ fbhh,
    const float* __restrict__ bWih, const float* __restrict__ bbih, const float* __restrict__ bbhh)
{
    __shared__ float As[16][256];   // duplicated pairs: As[k][2m]=As[k][2m+1]=A(m,k)
    __shared__ float Bs[16][128];

    const int dir   = blockIdx.z;
    const int s     = blockIdx.x;
    const int ntile = blockIdx.y;
    const float* W  = dir ? bWih : fWih;
    const float* bi = dir ? bbih : fbih;
    const float* bh = dir ? bbhh : fbhh;
    const int src_s = dir ? ((S_LEN - s) & (S_LEN - 1)) : s;
    const float* Abase = g_seq_emb + (size_t)src_s * BSZ * EDIM;

    const int t   = threadIdx.x;
    const int lr  = t & 127;
    const int lqp = t >> 7;
    const int tm  = t >> 4;
    const int tn  = t & 15;

    unsigned long long acc2[8][4];
#pragma unroll
    for (int i = 0; i < 8; i++)
#pragma unroll
        for (int j = 0; j < 4; j++) acc2[i][j] = 0ULL;

    const int NK = (EDIM + 15) / 16;   // 19
    for (int kt = 0; kt < NK; kt++) {
        float4 av[2], bv[2];
#pragma unroll
        for (int q = 0; q < 2; q++) {
            const int kk = kt * 16 + (lqp * 2 + q) * 4;
            av[q] = make_float4(0.f, 0.f, 0.f, 0.f);
            bv[q] = make_float4(0.f, 0.f, 0.f, 0.f);
            if (kk + 3 < EDIM) {
                av[q] = *(const float4*)(Abase + (size_t)lr * EDIM + kk);
                bv[q] = *(const float4*)(W + (size_t)(ntile * 128 + lr) * EDIM + kk);
            }
        }
        __syncthreads();
#pragma unroll
        for (int q = 0; q < 2; q++) {
            const int kb = (lqp * 2 + q) * 4;
            As[kb + 0][2 * lr] = av[q].x; As[kb + 0][2 * lr + 1] = av[q].x;
            As[kb + 1][2 * lr] = av[q].y; As[kb + 1][2 * lr + 1] = av[q].y;
            As[kb + 2][2 * lr] = av[q].z; As[kb + 2][2 * lr + 1] = av[q].z;
            As[kb + 3][2 * lr] = av[q].w; As[kb + 3][2 * lr + 1] = av[q].w;
            Bs[kb + 0][lr] = bv[q].x; Bs[kb + 1][lr] = bv[q].y;
            Bs[kb + 2][lr] = bv[q].z; Bs[kb + 3][lr] = bv[q].w;
        }
        __syncthreads();
#pragma unroll
        for (int k = 0; k < 16; k++) {
            // LDS.128 loads (conflict-light) instead of scalar LDS.64
            const ulonglong2* ap2 = (const ulonglong2*)((const unsigned long long*)&As[k][0] + tm * 8);
            const ulonglong2* bp2 = (const ulonglong2*)((const unsigned long long*)&Bs[k][0] + tn * 4);
            ulonglong2 b01 = bp2[0], b23 = bp2[1];
            ulonglong2 a01 = ap2[0], a23 = ap2[1], a45 = ap2[2], a67 = ap2[3];
            unsigned long long a[8] = {a01.x, a01.y, a23.x, a23.y, a45.x, a45.y, a67.x, a67.y};
#pragma unroll
            for (int i = 0; i < 8; i++) {
                fma2(acc2[i][0], a[i], b01.x);
                fma2(acc2[i][1], a[i], b01.y);
                fma2(acc2[i][2], a[i], b23.x);
                fma2(acc2[i][3], a[i], b23.y);
            }
        }
    }
    const int ncol0 = ntile * 128 + tn * 8;
    float bias[8];
#pragma unroll
    for (int j = 0; j < 8; j++) bias[j] = bi[ncol0 + j] + bh[ncol0 + j];
#pragma unroll
    for (int i = 0; i < 8; i++) {
        const int ro = s * 128 + tm * 8 + i;
        float* orow = g_gx[dir] + (size_t)ro * 1024 + ncol0;
#pragma unroll
        for (int j = 0; j < 4; j++) {
            float2 v = upk2(acc2[i][j]);
            orow[2 * j]     = v.x + bias[2 * j];
            orow[2 * j + 1] = v.y + bias[2 * j + 1];
        }
    }
}

// ---------------- kernel 3: LSTM recurrence (both directions) ---------------
// G=4 batch rows per block. Thread u owns hidden unit u. Per k: ONE coalesced
// LDG.128 = (w_i,w_f,w_g,w_o)[u][k]; h kept in smem as duplicated f32x2 pairs
// so gate-pairs (i,f) and (g,o) accumulate in packed FFMA2 with no dup-MOVs.
__global__ __launch_bounds__(256) void lstm_kernel()
{
    const int G = 4;
    const int dir = blockIdx.y;
    const int b0  = blockIdx.x * G;
    const float* gx = g_gx[dir];
    const int u = threadIdx.x;
    const ulonglong2* W2 = (const ulonglong2*)&g_Wt4[dir][0][0][0];  // [k*256+u] -> (if | go)

    __shared__ unsigned long long hd[2][G][HDIM];   // (h,h) duplicated pairs
    float c[G], h[G];
#pragma unroll
    for (int b = 0; b < G; b++) { c[b] = 0.0f; h[b] = 0.0f; hd[0][b][u] = 0ULL; }
    __syncthreads();

    for (int s = 0; s < S_LEN; s++) {
        const int cur = s & 1, nxt = cur ^ 1;
        const float* gxs = gx + ((size_t)s * BSZ + b0) * 1024;
        float gxv[4][G];
#pragma unroll
        for (int g = 0; g < 4; g++)
#pragma unroll
            for (int b = 0; b < G; b++) gxv[g][b] = gxs[b * 1024 + g * HDIM + u];

        unsigned long long aif[G], ago[G];
#pragma unroll
        for (int b = 0; b < G; b++) { aif[b] = 0ULL; ago[b] = 0ULL; }

        const unsigned long long* h0p = &hd[cur][0][0];
        const unsigned long long* h1p = &hd[cur][1][0];
        const unsigned long long* h2p = &hd[cur][2][0];
        const unsigned long long* h3p = &hd[cur][3][0];

#pragma unroll 4
        for (int k = 0; k < HDIM; k++) {
            ulonglong2 w = W2[k * HDIM + u];          // coalesced LDG.128
            unsigned long long hh0 = h0p[k], hh1 = h1p[k], hh2 = h2p[k], hh3 = h3p[k];
            fma2(aif[0], w.x, hh0); fma2(ago[0], w.y, hh0);
            fma2(aif[1], w.x, hh1); fma2(ago[1], w.y, hh1);
            fma2(aif[2], w.x, hh2); fma2(ago[2], w.y, hh2);
            fma2(aif[3], w.x, hh3); fma2(ago[3], w.y, hh3);
        }
#pragma unroll
        for (int b = 0; b < G; b++) {
            float2 vif = upk2(aif[b]);
            float2 vgo = upk2(ago[b]);
            float gi = gxv[0][b] + vif.x;
            float gf = gxv[1][b] + vif.y;
            float gg = gxv[2][b] + vgo.x;
            float go = gxv[3][b] + vgo.y;
            float cc = sigmoidf_(gf) * c[b] + sigmoidf_(gi) * tanhf_(gg);
            c[b] = cc;
            h[b] = sigmoidf_(go) * tanhf_(cc);
            hd[nxt][b][u] = pk2(h[b], h[b]);
        }
        __syncthreads();
    }
#pragma unroll
    for (int b = 0; b < G; b++)
        g_h0[(size_t)(b0 + b) * (2 * HDIM) + dir * HDIM + u] = h[b];
}

// ---------------- kernel 4: decoder input gates (per class, batch-invariant)-
__global__ __launch_bounds__(256) void dec_prep_kernel(
    const int* __restrict__ classes, const float* __restrict__ ecW,
    const float* __restrict__ dWih, const float* __restrict__ dbih)
{
    __shared__ float ce[EDIM];
    const int c = blockIdx.x;
    const int cls = classes[c];
    for (int e = threadIdx.x; e < EDIM; e += blockDim.x)
        ce[e] = tanhf_(ecW[(size_t)cls * EDIM + e]);
    __syncthreads();
    const int j = blockIdx.y * 256 + threadIdx.x;    // 6*256 = 1536 outputs
    float acc = dbih[j];
    const float4* w = (const float4*)(dWih + (size_t)j * EDIM);
#pragma unroll 5
    for (int k = 0; k < EDIM / 4; k++) {
        float4 wv = w[k];
        acc += wv.x * ce[4 * k] + wv.y * ce[4 * k + 1] + wv.z * ce[4 * k + 2] + wv.w * ce[4 * k + 3];
    }
    g_gxc[c * 1536 + j] = acc;
}

// ---------------- kernel 5: decoder GRU + proj + cls + log_softmax ----------
// Gd=2 batch rows per block, 512 threads; coalesced transposed weights.
__global__ __launch_bounds__(512) void dec_kernel(
    const float* __restrict__ dbhh,
    const float* __restrict__ projW, const float* __restrict__ projB,
    const float* __restrict__ clsW, const float* __restrict__ clsB,
    float* __restrict__ out)
{
    const int Gd = 2;
    const int H2 = 2 * HDIM;     // 512
    const int b0 = blockIdx.x * Gd;
    const int u  = threadIdx.x;
    const ulonglong2* W2 = (const ulonglong2*)&g_dWt4[0][0][0];  // [k*512+u] -> (rz | n,pad)

    __shared__ unsigned long long hd[2][Gd][512];   // duplicated (h,h) pairs
    __shared__ float hplain[Gd][512];
    __shared__ float projs[Gd][PDIM];
    __shared__ float lgs[Gd][2];

    float hprev[Gd];
#pragma unroll
    for (int b = 0; b < Gd; b++) {
        hprev[b] = g_h0[(size_t)(b0 + b) * H2 + u];
        hd[0][b][u] = pk2(hprev[b], hprev[b]);
    }
    const float bhr = dbhh[u], bhz = dbhh[H2 + u], bhn = dbhh[2 * H2 + u];
    __syncthreads();

    for (int c = 0; c < NCLS; c++) {
        const int cur = c & 1, nxt = cur ^ 1;
        unsigned long long arz[Gd], anp[Gd];
#pragma unroll
        for (int b = 0; b < Gd; b++) { arz[b] = 0ULL; anp[b] = 0ULL; }
        const unsigned long long* h0p = &hd[cur][0][0];
        const unsigned long long* h1p = &hd[cur][1][0];

#pragma unroll 4
        for (int k = 0; k < H2; k++) {
            ulonglong2 w = W2[k * H2 + u];            // coalesced LDG.128
            unsigned long long hh0 = h0p[k], hh1 = h1p[k];
            fma2(arz[0], w.x, hh0); fma2(anp[0], w.y, hh0);
            fma2(arz[1], w.x, hh1); fma2(anp[1], w.y, hh1);
        }
        const float gxr = g_gxc[c * 1536 + u];
        const float gxz = g_gxc[c * 1536 + H2 + u];
        const float gxn = g_gxc[c * 1536 + 2 * H2 + u];
#pragma unroll
        for (int b = 0; b < Gd; b++) {
            float2 vrz = upk2(arz[b]);
            float2 vnp = upk2(anp[b]);
            float r = sigmoidf_(gxr + vrz.x + bhr);
            float z = sigmoidf_(gxz + vrz.y + bhz);
            float n = tanhf_(gxn + r * (vnp.x + bhn));
            float hn = tanhf_((1.0f - z) * n + z * hprev[b]);
            hprev[b] = hn;
            hd[nxt][b][u] = pk2(hn, hn);
            hplain[b][u] = hn;
        }
        __syncthreads();

        // projection: thread u -> (b = u>>8, p = u&255), dot over 512
        {
            const int b = u >> 8, p = u & 255;
            const float4* w = (const float4*)(projW + (size_t)p * H2);
            const float4* hv = (const float4*)hplain[b];
            float acc = projB[p];
            for (int k4 = 0; k4 < H2 / 4; k4++) {
                float4 wv = w[k4], hvv = hv[k4];
                acc += wv.x * hvv.x + wv.y * hvv.y + wv.z * hvv.z + wv.w * hvv.w;
            }
            projs[b][p] = acc;
        }
        __syncthreads();

        const int wid = u >> 5, lid = u & 31;
        if (wid < Gd * 2) {
            const int b = wid >> 1, cl = wid & 1;
            float acc = 0.0f;
            for (int k = lid; k < PDIM; k += 32) acc += clsW[cl * PDIM + k] * projs[b][k];
#pragma unroll
            for (int o = 16; o > 0; o >>= 1) acc += __shfl_down_sync(0xffffffffu, acc, o);
            if (lid == 0) lgs[b][cl] = acc + clsB[cl];
        }
        __syncthreads();
        if (u < Gd) {
            const int b = u;
            float l0 = lgs[b][0], l1 = lgs[b][1];
            float m = fmaxf(l0, l1);
            float lse = m + logf(expf(l0 - m) + expf(l1 - m));
            out[(size_t)c * BSZ * 2 + (b0 + b) * 2 + 0] = l0 - lse;
            out[(size_t)c * BSZ * 2 + (b0 + b) * 2 + 1] = l1 - lse;
        }
        __syncthreads();
    }
}

// ---------------- launch -----------------------------------------------------
extern "C" void kernel_launch(void* const* d_in, const int* in_sizes, int n_in,
                              void* d_out, int out_size)
{
    const int*   seq     = (const int*)d_in[0];
    const int*   classes = (const int*)d_in[1];
    const float* embW    = (const float*)d_in[2];
    const float* ecW     = (const float*)d_in[3];
    const float* fWih    = (const float*)d_in[4];
    const float* fWhh    = (const float*)d_in[5];
    const float* fbih    = (const float*)d_in[6];
    const float* fbhh    = (const float*)d_in[7];
    const float* bWih    = (const float*)d_in[8];
    const float* bWhh    = (const float*)d_in[9];
    const float* bbih    = (const float*)d_in[10];
    const float* bbhh    = (const float*)d_in[11];
    const float* dWih    = (const float*)d_in[12];
    const float* dWhh    = (const float*)d_in[13];
    const float* dbih    = (const float*)d_in[14];
    const float* dbhh    = (const float*)d_in[15];
    const float* projW   = (const float*)d_in[16];
    const float* projB   = (const float*)d_in[17];
    const float* clsW    = (const float*)d_in[18];
    const float* clsB    = (const float*)d_in[19];
    float* out = (float*)d_out;

    {   // 0. weight transposes (coalesced recurrence layouts)
        dim3 gl(HDIM / 32, HDIM / 32, 8);          // 2 dirs x 4 gates
        transpose_lstm_w<<<gl, 1024>>>(fWhh, bWhh);
        dim3 gd(2 * HDIM / 32, 2 * HDIM / 32, 3);  // 3 gates
        transpose_dec_w<<<gd, 1024>>>(dWhh);
    }
    {   // 1. embeddings (time-major) + tanh
        long long total = (long long)S_LEN * BSZ * EDIM;
        int blocks = (int)((total + 255) / 256);
        embed_kernel<<<blocks, 256>>>(seq, embW);
    }
    {   // 2. input-gate GEMMs for both directions (biases folded)
        dim3 grid(S_LEN, 1024 / 128, 2);
        gx_gemm_kernel<<<grid, 256>>>(fWih, fbih, fbhh, bWih, bbih, bbhh);
    }
    {   // 3. bidirectional LSTM recurrence
        dim3 grid(BSZ / 4, 2);
        lstm_kernel<<<grid, 256>>>();
    }
    {   // 4. decoder input gates per class
        dim3 grid(NCLS, 6);
        dec_prep_kernel<<<grid, 256>>>(classes, ecW, dWih, dbih);
    }
    {   // 5. decoder GRU + projection + classifier + log_softmax
        dec_kernel<<<BSZ / 2, 512>>>(dbhh, projW, projB, clsW, clsB, out);
    }
    (void)in_sizes; (void)n_in; (void)out_size;
}

// round 4
// speedup vs baseline: 2.1767x; 1.1918x over previous
#include <cuda_runtime.h>
#include <cuda_bf16.h>
#include <math.h>

#define S_LEN 512
#define BSZ   128
#define EDIM  300
#define HDIM  256
#define NCLS  6
#define PDIM  256
#define NCTA_LSTM 128            // 64 u-slices x 2 dirs, all co-resident (<148 SMs)

// ---------------- scratch (device globals; no runtime allocation) ----------
__device__ float g_seq_emb[(size_t)S_LEN * BSZ * EDIM];              // 78.6 MB
__device__ float g_gx[2][(size_t)S_LEN * 4 * HDIM * BSZ];            // [dir][s][col][b] 536 MB
__device__ float g_h[2][2][HDIM][BSZ];                               // [dir][buf][u][b] 512 KB
__device__ float g_h0[(size_t)BSZ * 2 * HDIM];                       // concat [fh, bh]
__device__ float g_gxc[NCLS * 3 * 2 * HDIM];                         // decoder input gates
__device__ float g_Wt4[2][HDIM][HDIM][4];                            // [dir][k][u][gate i,f,g,o]
__device__ float g_dWt4[2 * HDIM][2 * HDIM][4];                      // [k][u][gate r,z,n,pad]
__device__ int   g_bar_cnt;                                          // spin barrier state
__device__ volatile int g_bar_flag;

// ---------------- helpers ---------------------------------------------------
__device__ __forceinline__ float sigmoidf_(float x) { return 1.0f / (1.0f + expf(-x)); }
__device__ __forceinline__ float tanhf_(float x) { return 1.0f - 2.0f / (expf(2.0f * x) + 1.0f); }

__device__ __forceinline__ unsigned long long pk2(float lo, float hi) {
    return ((unsigned long long)__float_as_uint(hi) << 32) | (unsigned long long)__float_as_uint(lo);
}
__device__ __forceinline__ float2 upk2(unsigned long long u) {
    float2 f; f.x = __uint_as_float((unsigned)u); f.y = __uint_as_float((unsigned)(u >> 32)); return f;
}
__device__ __forceinline__ void fma2(unsigned long long& d, unsigned long long a, unsigned long long b) {
    asm("fma.rn.f32x2 %0, %1, %2, %0;" : "+l"(d) : "l"(a), "l"(b));
}

// ---------------- kernel 0a: transpose LSTM Whh + reset barrier -------------
__global__ __launch_bounds__(1024) void transpose_lstm_w(const float* __restrict__ fWhh,
                                                         const float* __restrict__ bWhh)
{
    if (blockIdx.x == 0 && blockIdx.y == 0 && blockIdx.z == 0 && threadIdx.x == 0) {
        g_bar_cnt = 0; g_bar_flag = 0;
    }
    __shared__ float t[32][33];
    const int dir = blockIdx.z >> 2;
    const int g   = blockIdx.z & 3;
    const int k0  = blockIdx.x * 32;
    const int u0  = blockIdx.y * 32;
    const int tx = threadIdx.x & 31, ty = threadIdx.x >> 5;
    const float* W = dir ? bWhh : fWhh;
    t[ty][tx] = W[(size_t)(g * HDIM + u0 + ty) * HDIM + k0 + tx];
    __syncthreads();
    g_Wt4[dir][k0 + ty][u0 + tx][g] = t[tx][ty];
}

// ---------------- kernel 0b: transpose decoder Whh ---------------------------
__global__ __launch_bounds__(1024) void transpose_dec_w(const float* __restrict__ dWhh)
{
    __shared__ float t[32][33];
    const int g  = blockIdx.z;
    const int k0 = blockIdx.x * 32;
    const int u0 = blockIdx.y * 32;
    const int tx = threadIdx.x & 31, ty = threadIdx.x >> 5;
    t[ty][tx] = dWhh[(size_t)(g * 2 * HDIM + u0 + ty) * (2 * HDIM) + k0 + tx];
    __syncthreads();
    g_dWt4[k0 + ty][u0 + tx][g] = t[tx][ty];
}

// ---------------- kernel 1: embedding gather + tanh, time-major -------------
__global__ void embed_kernel(const int* __restrict__ seq, const float* __restrict__ embW) {
    long long idx = (long long)blockIdx.x * blockDim.x + threadIdx.x;
    const long long total = (long long)S_LEN * BSZ * EDIM;
    if (idx >= total) return;
    int e = (int)(idx % EDIM);
    int r = (int)(idx / EDIM);
    int b = r % BSZ;
    int s = r / BSZ;
    int v = seq[b * S_LEN + s];
    g_seq_emb[idx] = tanhf_(embW[(long long)v * EDIM + e]);
}

// ---------------- kernel 2: input GEMMs, output TRANSPOSED [s][col][b] ------
// M-dim of tile = 128 gate-cols (W rows), N-dim = 128 batch. b-split tiling:
// thread (tm,tn): cols tm*8+i, batches {4tn..4tn+3} u {64+4tn..+3} -> STG.128.
__global__ __launch_bounds__(256) void gx_gemm_kernel(
    const float* __restrict__ fWih, const float* __restrict__ fbih, const float* __restrict__ fbhh,
    const float* __restrict__ bWih, const float* __restrict__ bbih, const float* __restrict__ bbhh)
{
    __shared__ float As[16][256];   // W cols duplicated pairs
    __shared__ float Bs[16][128];   // emb batch rows

    const int dir   = blockIdx.z;
    const int s     = blockIdx.x;
    const int ntile = blockIdx.y;
    const float* W  = dir ? bWih : fWih;
    const float* bi = dir ? bbih : fbih;
    const float* bh = dir ? bbhh : fbhh;
    const int src_s = dir ? ((S_LEN - s) & (S_LEN - 1)) : s;
    const float* Abase = g_seq_emb + (size_t)src_s * BSZ * EDIM;

    const int t   = threadIdx.x;
    const int lr  = t & 127;
    const int lqp = t >> 7;
    const int tm  = t >> 4;            // col group
    const int tn  = t & 15;            // batch group

    unsigned long long acc2[8][4];
#pragma unroll
    for (int i = 0; i < 8; i++)
#pragma unroll
        for (int j = 0; j < 4; j++) acc2[i][j] = 0ULL;

    const int NK = (EDIM + 15) / 16;   // 19
    for (int kt = 0; kt < NK; kt++) {
        float4 av[2], bv[2];
#pragma unroll
        for (int q = 0; q < 2; q++) {
            const int kk = kt * 16 + (lqp * 2 + q) * 4;
            av[q] = make_float4(0.f, 0.f, 0.f, 0.f);
            bv[q] = make_float4(0.f, 0.f, 0.f, 0.f);
            if (kk + 3 < EDIM) {
                av[q] = *(const float4*)(W + (size_t)(ntile * 128 + lr) * EDIM + kk);   // cols
                bv[q] = *(const float4*)(Abase + (size_t)lr * EDIM + kk);               // batch
            }
        }
        __syncthreads();
#pragma unroll
        for (int q = 0; q < 2; q++) {
            const int kb = (lqp * 2 + q) * 4;
            As[kb + 0][2 * lr] = av[q].x; As[kb + 0][2 * lr + 1] = av[q].x;
            As[kb + 1][2 * lr] = av[q].y; As[kb + 1][2 * lr + 1] = av[q].y;
            As[kb + 2][2 * lr] = av[q].z; As[kb + 2][2 * lr + 1] = av[q].z;
            As[kb + 3][2 * lr] = av[q].w; As[kb + 3][2 * lr + 1] = av[q].w;
            Bs[kb + 0][lr] = bv[q].x; Bs[kb + 1][lr] = bv[q].y;
            Bs[kb + 2][lr] = bv[q].z; Bs[kb + 3][lr] = bv[q].w;
        }
        __syncthreads();
#pragma unroll
        for (int k = 0; k < 16; k++) {
            const ulonglong2* ap2 = (const ulonglong2*)((const unsigned long long*)&As[k][0] + tm * 8);
            ulonglong2 a01 = ap2[0], a23 = ap2[1], a45 = ap2[2], a67 = ap2[3];
            // b pairs: (4tn,4tn+1),(4tn+2,4tn+3) and +64
            ulonglong2 bA = *(const ulonglong2*)((const unsigned long long*)&Bs[k][0] + tn * 2);
            ulonglong2 bB = *(const ulonglong2*)((const unsigned long long*)&Bs[k][64] + tn * 2);
            unsigned long long a[8] = {a01.x, a01.y, a23.x, a23.y, a45.x, a45.y, a67.x, a67.y};
#pragma unroll
            for (int i = 0; i < 8; i++) {
                fma2(acc2[i][0], a[i], bA.x);
                fma2(acc2[i][1], a[i], bA.y);
                fma2(acc2[i][2], a[i], bB.x);
                fma2(acc2[i][3], a[i], bB.y);
            }
        }
    }
    // epilogue: per-col bias, transposed store [s][col][b], coalesced STG.128
    float* gbase = g_gx[dir] + (size_t)s * 1024 * 128;
#pragma unroll
    for (int i = 0; i < 8; i++) {
        const int col = ntile * 128 + tm * 8 + i;
        const float bb = bi[col] + bh[col];
        float2 v0 = upk2(acc2[i][0]), v1 = upk2(acc2[i][1]);
        float2 v2 = upk2(acc2[i][2]), v3 = upk2(acc2[i][3]);
        float4 oA = make_float4(v0.x + bb, v0.y + bb, v1.x + bb, v1.y + bb);
        float4 oB = make_float4(v2.x + bb, v2.y + bb, v3.x + bb, v3.y + bb);
        *(float4*)(gbase + (size_t)col * 128 + 4 * tn)      = oA;
        *(float4*)(gbase + (size_t)col * 128 + 64 + 4 * tn) = oB;
    }
}

// ---------------- kernel 3: persistent LSTM, smem-resident weights ----------
// 128 CTAs x 128 threads. CTA: dir = cta&1, u-slice u0 = (cta>>1)*4.
// Warp rg owns unit u0+rg (all 4 gates), lane bq owns batches 4bq..4bq+3.
// Weights (32KB) in smem; h exchanged via L2 with a spin barrier per step.
__global__ __launch_bounds__(128) void lstm_persist()
{
    extern __shared__ char smraw[];
    unsigned long long (*wd)[4][4] = (unsigned long long(*)[4][4])smraw;        // [256][ui][g] dup, 32KB
    float* hs = (float*)(smraw + 256 * 16 * 8);                                  // [64][128], 32KB

    const int cta = blockIdx.x;
    const int dir = cta & 1;
    const int u0  = (cta >> 1) * 4;
    const int t   = threadIdx.x;
    const int rg  = t >> 5;            // warp = unit index
    const int bq  = t & 31;            // batch quad
    const int u   = u0 + rg;

    // load weights (dup pairs) into smem
    for (int e = t; e < 256 * 16; e += 128) {
        int k = e >> 4, ui = (e >> 2) & 3, g = e & 3;
        float w = g_Wt4[dir][k][u0 + ui][g];
        wd[k][ui][g] = pk2(w, w);
    }
    // zero h buf0 for this CTA's units
    *(float4*)&g_h[dir][0][u][4 * bq] = make_float4(0.f, 0.f, 0.f, 0.f);
    float c[4] = {0.f, 0.f, 0.f, 0.f};
    float hnew[4] = {0.f, 0.f, 0.f, 0.f};
    __threadfence();
    __syncthreads();
    // ---- global barrier helper (inline each use) ----
    int epoch = 1;
    {
        if (t == 0) {
            int v = atomicAdd(&g_bar_cnt, 1);
            if (v == epoch * NCTA_LSTM - 1) { g_bar_flag = epoch; __threadfence(); }
            else { while (g_bar_flag < epoch) __nanosleep(40); }
        }
        __syncthreads();
    }

    const float* gxd = g_gx[dir];

    for (int s = 0; s < S_LEN; s++) {
        const int buf = s & 1;
        const float* hsrc = &g_h[dir][buf][0][0];

        // prefetch gx for this step (used at the end)
        float4 gxq[4];
#pragma unroll
        for (int g = 0; g < 4; g++)
            gxq[g] = __ldcg((const float4*)(gxd + ((size_t)s * 1024 + g * 256 + u) * 128 + 4 * bq));

        unsigned long long acc[4][2];
#pragma unroll
        for (int g = 0; g < 4; g++) { acc[g][0] = 0ULL; acc[g][1] = 0ULL; }

        // prefetch h chunk 0 into registers
        float4 pf[16];
#pragma unroll
        for (int i = 0; i < 16; i++) pf[i] = __ldcg((const float4*)(hsrc + i * 512 + t * 4));

        for (int cch = 0; cch < 4; cch++) {
            __syncthreads();
#pragma unroll
            for (int i = 0; i < 16; i++) *(float4*)(hs + i * 512 + t * 4) = pf[i];
            __syncthreads();
            if (cch < 3) {
                const float* src = hsrc + (cch + 1) * 8192;
#pragma unroll
                for (int i = 0; i < 16; i++) pf[i] = __ldcg((const float4*)(src + i * 512 + t * 4));
            }
            const int kb = cch * 64;
#pragma unroll 8
            for (int kk = 0; kk < 64; kk++) {
                ulonglong2 h01 = *(const ulonglong2*)(hs + kk * 128 + 4 * bq);   // (b0,b1)|(b2,b3)
                ulonglong2 wif = *(const ulonglong2*)&wd[kb + kk][rg][0];
                ulonglong2 wgo = *(const ulonglong2*)&wd[kb + kk][rg][2];
                fma2(acc[0][0], wif.x, h01.x); fma2(acc[0][1], wif.x, h01.y);
                fma2(acc[1][0], wif.y, h01.x); fma2(acc[1][1], wif.y, h01.y);
                fma2(acc[2][0], wgo.x, h01.x); fma2(acc[2][1], wgo.x, h01.y);
                fma2(acc[3][0], wgo.y, h01.x); fma2(acc[3][1], wgo.y, h01.y);
            }
        }
        // cell update for 4 batches
        const float* gx0 = (const float*)&gxq[0];
        const float* gx1 = (const float*)&gxq[1];
        const float* gx2 = (const float*)&gxq[2];
        const float* gx3 = (const float*)&gxq[3];
#pragma unroll
        for (int j = 0; j < 4; j++) {
            const int p = j >> 1, l = j & 1;
            float2 vi = upk2(acc[0][p]), vf = upk2(acc[1][p]);
            float2 vg = upk2(acc[2][p]), vo = upk2(acc[3][p]);
            float gi = gx0[j] + (l ? vi.y : vi.x);
            float gf = gx1[j] + (l ? vf.y : vf.x);
            float gg = gx2[j] + (l ? vg.y : vg.x);
            float go = gx3[j] + (l ? vo.y : vo.x);
            float cc = sigmoidf_(gf) * c[j] + sigmoidf_(gi) * tanhf_(gg);
            c[j] = cc;
            hnew[j] = sigmoidf_(go) * tanhf_(cc);
        }
        float4 hv = make_float4(hnew[0], hnew[1], hnew[2], hnew[3]);
        __stcg((float4*)&g_h[dir][buf ^ 1][u][4 * bq], hv);
        __threadfence();
        // global barrier
        epoch++;
        if (t == 0) {
            int v = atomicAdd(&g_bar_cnt, 1);
            if (v == epoch * NCTA_LSTM - 1) { g_bar_flag = epoch; __threadfence(); }
            else { while (g_bar_flag < epoch) __nanosleep(40); }
        }
        __syncthreads();
    }
    // write final h to g_h0 [b][dir*256+u]
#pragma unroll
    for (int j = 0; j < 4; j++)
        g_h0[(size_t)(4 * bq + j) * (2 * HDIM) + dir * HDIM + u] = hnew[j];
}

// ---------------- kernel 4: decoder input gates ------------------------------
__global__ __launch_bounds__(256) void dec_prep_kernel(
    const int* __restrict__ classes, const float* __restrict__ ecW,
    const float* __restrict__ dWih, const float* __restrict__ dbih)
{
    __shared__ float ce[EDIM];
    const int c = blockIdx.x;
    const int cls = classes[c];
    for (int e = threadIdx.x; e < EDIM; e += blockDim.x)
        ce[e] = tanhf_(ecW[(size_t)cls * EDIM + e]);
    __syncthreads();
    const int j = blockIdx.y * 256 + threadIdx.x;
    float acc = dbih[j];
    const float4* w = (const float4*)(dWih + (size_t)j * EDIM);
#pragma unroll 5
    for (int k = 0; k < EDIM / 4; k++) {
        float4 wv = w[k];
        acc += wv.x * ce[4 * k] + wv.y * ce[4 * k + 1] + wv.z * ce[4 * k + 2] + wv.w * ce[4 * k + 3];
    }
    g_gxc[c * 1536 + j] = acc;
}

// ---------------- kernel 5: decoder GRU + proj + cls + log_softmax ----------
__global__ __launch_bounds__(512) void dec_kernel(
    const float* __restrict__ dbhh,
    const float* __restrict__ projW, const float* __restrict__ projB,
    const float* __restrict__ clsW, const float* __restrict__ clsB,
    float* __restrict__ out)
{
    const int Gd = 2;
    const int H2 = 2 * HDIM;
    const int b0 = blockIdx.x * Gd;
    const int u  = threadIdx.x;
    const ulonglong2* W2 = (const ulonglong2*)&g_dWt4[0][0][0];

    __shared__ unsigned long long hd[2][Gd][512];
    __shared__ float hplain[Gd][512];
    __shared__ float projs[Gd][PDIM];
    __shared__ float lgs[Gd][2];

    float hprev[Gd];
#pragma unroll
    for (int b = 0; b < Gd; b++) {
        hprev[b] = g_h0[(size_t)(b0 + b) * H2 + u];
        hd[0][b][u] = pk2(hprev[b], hprev[b]);
    }
    const float bhr = dbhh[u], bhz = dbhh[H2 + u], bhn = dbhh[2 * H2 + u];
    __syncthreads();

    for (int c = 0; c < NCLS; c++) {
        const int cur = c & 1, nxt = cur ^ 1;
        unsigned long long arz[Gd], anp[Gd];
#pragma unroll
        for (int b = 0; b < Gd; b++) { arz[b] = 0ULL; anp[b] = 0ULL; }
        const unsigned long long* h0p = &hd[cur][0][0];
        const unsigned long long* h1p = &hd[cur][1][0];

#pragma unroll 4
        for (int k = 0; k < H2; k++) {
            ulonglong2 w = W2[k * H2 + u];
            unsigned long long hh0 = h0p[k], hh1 = h1p[k];
            fma2(arz[0], w.x, hh0); fma2(anp[0], w.y, hh0);
            fma2(arz[1], w.x, hh1); fma2(anp[1], w.y, hh1);
        }
        const float gxr = g_gxc[c * 1536 + u];
        const float gxz = g_gxc[c * 1536 + H2 + u];
        const float gxn = g_gxc[c * 1536 + 2 * H2 + u];
#pragma unroll
        for (int b = 0; b < Gd; b++) {
            float2 vrz = upk2(arz[b]);
            float2 vnp = upk2(anp[b]);
            float r = sigmoidf_(gxr + vrz.x + bhr);
            float z = sigmoidf_(gxz + vrz.y + bhz);
            float n = tanhf_(gxn + r * (vnp.x + bhn));
            float hn = tanhf_((1.0f - z) * n + z * hprev[b]);
            hprev[b] = hn;
            hd[nxt][b][u] = pk2(hn, hn);
            hplain[b][u] = hn;
        }
        __syncthreads();
        {
            const int b = u >> 8, p = u & 255;
            const float4* w = (const float4*)(projW + (size_t)p * H2);
            const float4* hv = (const float4*)hplain[b];
            float acc = projB[p];
            for (int k4 = 0; k4 < H2 / 4; k4++) {
                float4 wv = w[k4], hvv = hv[k4];
                acc += wv.x * hvv.x + wv.y * hvv.y + wv.z * hvv.z + wv.w * hvv.w;
            }
            projs[b][p] = acc;
        }
        __syncthreads();
        const int wid = u >> 5, lid = u & 31;
        if (wid < Gd * 2) {
            const int b = wid >> 1, cl = wid & 1;
            float acc = 0.0f;
            for (int k = lid; k < PDIM; k += 32) acc += clsW[cl * PDIM + k] * projs[b][k];
#pragma unroll
            for (int o = 16; o > 0; o >>= 1) acc += __shfl_down_sync(0xffffffffu, acc, o);
            if (lid == 0) lgs[b][cl] = acc + clsB[cl];
        }
        __syncthreads();
        if (u < Gd) {
            const int b = u;
            float l0 = lgs[b][0], l1 = lgs[b][1];
            float m = fmaxf(l0, l1);
            float lse = m + logf(expf(l0 - m) + expf(l1 - m));
            out[(size_t)c * BSZ * 2 + (b0 + b) * 2 + 0] = l0 - lse;
            out[(size_t)c * BSZ * 2 + (b0 + b) * 2 + 1] = l1 - lse;
        }
        __syncthreads();
    }
}

// ---------------- launch -----------------------------------------------------
extern "C" void kernel_launch(void* const* d_in, const int* in_sizes, int n_in,
                              void* d_out, int out_size)
{
    const int*   seq     = (const int*)d_in[0];
    const int*   classes = (const int*)d_in[1];
    const float* embW    = (const float*)d_in[2];
    const float* ecW     = (const float*)d_in[3];
    const float* fWih    = (const float*)d_in[4];
    const float* fWhh    = (const float*)d_in[5];
    const float* fbih    = (const float*)d_in[6];
    const float* fbhh    = (const float*)d_in[7];
    const float* bWih    = (const float*)d_in[8];
    const float* bWhh    = (const float*)d_in[9];
    const float* bbih    = (const float*)d_in[10];
    const float* bbhh    = (const float*)d_in[11];
    const float* dWih    = (const float*)d_in[12];
    const float* dWhh    = (const float*)d_in[13];
    const float* dbih    = (const float*)d_in[14];
    const float* dbhh    = (const float*)d_in[15];
    const float* projW   = (const float*)d_in[16];
    const float* projB   = (const float*)d_in[17];
    const float* clsW    = (const float*)d_in[18];
    const float* clsB    = (const float*)d_in[19];
    float* out = (float*)d_out;

    static int smem_set = 0;
    const int lstm_smem = 256 * 16 * 8 + 64 * 128 * 4;   // 32KB wd + 32KB hs = 64KB
    if (!smem_set) {
        cudaFuncSetAttribute(lstm_persist, cudaFuncAttributeMaxDynamicSharedMemorySize, lstm_smem);
        smem_set = 1;
    }

    {   // 0. weight transposes + barrier reset
        dim3 gl(HDIM / 32, HDIM / 32, 8);
        transpose_lstm_w<<<gl, 1024>>>(fWhh, bWhh);
        dim3 gd(2 * HDIM / 32, 2 * HDIM / 32, 3);
        transpose_dec_w<<<gd, 1024>>>(dWhh);
    }
    {   // 1. embeddings
        long long total = (long long)S_LEN * BSZ * EDIM;
        int blocks = (int)((total + 255) / 256);
        embed_kernel<<<blocks, 256>>>(seq, embW);
    }
    {   // 2. input-gate GEMMs, transposed output
        dim3 grid(S_LEN, 1024 / 128, 2);
        gx_gemm_kernel<<<grid, 256>>>(fWih, fbih, fbhh, bWih, bbih, bbhh);
    }
    {   // 3. persistent bidirectional LSTM
        lstm_persist<<<NCTA_LSTM, 128, lstm_smem>>>();
    }
    {   // 4. decoder input gates per class
        dim3 grid(NCLS, 6);
        dec_prep_kernel<<<grid, 256>>>(classes, ecW, dWih, dbih);
    }
    {   // 5. decoder GRU + projection + classifier + log_softmax
        dec_kernel<<<BSZ / 2, 512>>>(dbhh, projW, projB, clsW, clsB, out);
    }
    (void)in_sizes; (void)n_in; (void)out_size;
}

// round 5
// speedup vs baseline: 2.7636x; 1.2696x over previous
#include <cuda_runtime.h>
#include <cuda_bf16.h>
#include <math.h>

#define S_LEN 512
#define BSZ   128
#define EDIM  300
#define HDIM  256
#define NCLS  6
#define PDIM  256
#define NCTA_LSTM 128            // 64 u-slices x 2 dirs, all co-resident (<148 SMs)

// ---------------- scratch (device globals; no runtime allocation) ----------
__device__ float g_seq_emb[(size_t)S_LEN * BSZ * EDIM];              // 78.6 MB
__device__ float g_gx[2][(size_t)S_LEN * 4 * HDIM * BSZ];            // [dir][s][col][b] 536 MB
__device__ float g_h[2][2][HDIM][BSZ];                               // [dir][buf][u][b] 512 KB
__device__ float g_h0[(size_t)BSZ * 2 * HDIM];                       // concat [fh, bh]
__device__ float g_gxc[NCLS * 3 * 2 * HDIM];                         // decoder input gates
__device__ float g_Wt4[2][HDIM][HDIM][4];                            // [dir][k][u][gate i,f,g,o]
__device__ float g_dWt4[2 * HDIM][2 * HDIM][4];                      // [k][u][gate r,z,n,pad]
__device__ int   g_bar_cnt;                                          // spin barrier state
__device__ volatile int g_bar_flag;

// ---------------- helpers ---------------------------------------------------
__device__ __forceinline__ float sigmoidf_(float x) { return 1.0f / (1.0f + expf(-x)); }
__device__ __forceinline__ float tanhf_(float x) { return 1.0f - 2.0f / (expf(2.0f * x) + 1.0f); }

__device__ __forceinline__ unsigned long long pk2(float lo, float hi) {
    return ((unsigned long long)__float_as_uint(hi) << 32) | (unsigned long long)__float_as_uint(lo);
}
__device__ __forceinline__ float2 upk2(unsigned long long u) {
    float2 f; f.x = __uint_as_float((unsigned)u); f.y = __uint_as_float((unsigned)(u >> 32)); return f;
}
__device__ __forceinline__ void fma2(unsigned long long& d, unsigned long long a, unsigned long long b) {
    asm("fma.rn.f32x2 %0, %1, %2, %0;" : "+l"(d) : "l"(a), "l"(b));
}

// ---------------- kernel 0a: transpose LSTM Whh + reset barrier -------------
__global__ __launch_bounds__(1024) void transpose_lstm_w(const float* __restrict__ fWhh,
                                                         const float* __restrict__ bWhh)
{
    if (blockIdx.x == 0 && blockIdx.y == 0 && blockIdx.z == 0 && threadIdx.x == 0) {
        g_bar_cnt = 0; g_bar_flag = 0;
    }
    __shared__ float t[32][33];
    const int dir = blockIdx.z >> 2;
    const int g   = blockIdx.z & 3;
    const int k0  = blockIdx.x * 32;
    const int u0  = blockIdx.y * 32;
    const int tx = threadIdx.x & 31, ty = threadIdx.x >> 5;
    const float* W = dir ? bWhh : fWhh;
    t[ty][tx] = W[(size_t)(g * HDIM + u0 + ty) * HDIM + k0 + tx];
    __syncthreads();
    g_Wt4[dir][k0 + ty][u0 + tx][g] = t[tx][ty];
}

// ---------------- kernel 0b: transpose decoder Whh ---------------------------
__global__ __launch_bounds__(1024) void transpose_dec_w(const float* __restrict__ dWhh)
{
    __shared__ float t[32][33];
    const int g  = blockIdx.z;
    const int k0 = blockIdx.x * 32;
    const int u0 = blockIdx.y * 32;
    const int tx = threadIdx.x & 31, ty = threadIdx.x >> 5;
    t[ty][tx] = dWhh[(size_t)(g * 2 * HDIM + u0 + ty) * (2 * HDIM) + k0 + tx];
    __syncthreads();
    g_dWt4[k0 + ty][u0 + tx][g] = t[tx][ty];
}

// ---------------- kernel 1: embedding gather + tanh, time-major -------------
__global__ void embed_kernel(const int* __restrict__ seq, const float* __restrict__ embW) {
    long long idx = (long long)blockIdx.x * blockDim.x + threadIdx.x;
    const long long total = (long long)S_LEN * BSZ * EDIM;
    if (idx >= total) return;
    int e = (int)(idx % EDIM);
    int r = (int)(idx / EDIM);
    int b = r % BSZ;
    int s = r / BSZ;
    int v = seq[b * S_LEN + s];
    g_seq_emb[idx] = tanhf_(embW[(long long)v * EDIM + e]);
}

// ---------------- kernel 2: input GEMMs, output TRANSPOSED [s][col][b] ------
// A natural in smem; (a,a) f32x2 duplicates built in registers (alu pipe) so
// smem crossbar traffic drops to 64B/thread/k — balanced with the fma pipe.
__global__ __launch_bounds__(256) void gx_gemm_kernel(
    const float* __restrict__ fWih, const float* __restrict__ fbih, const float* __restrict__ fbhh,
    const float* __restrict__ bWih, const float* __restrict__ bbih, const float* __restrict__ bbhh)
{
    __shared__ float As[16][128];   // W cols (natural)
    __shared__ float Bs[16][128];   // emb batch rows (natural)

    const int dir   = blockIdx.z;
    const int s     = blockIdx.x;
    const int ntile = blockIdx.y;
    const float* W  = dir ? bWih : fWih;
    const float* bi = dir ? bbih : fbih;
    const float* bh = dir ? bbhh : fbhh;
    const int src_s = dir ? ((S_LEN - s) & (S_LEN - 1)) : s;
    const float* Abase = g_seq_emb + (size_t)src_s * BSZ * EDIM;

    const int t   = threadIdx.x;
    const int lr  = t & 127;
    const int lqp = t >> 7;
    const int tm  = t >> 4;            // col group
    const int tn  = t & 15;            // batch group

    unsigned long long acc2[8][4];
#pragma unroll
    for (int i = 0; i < 8; i++)
#pragma unroll
        for (int j = 0; j < 4; j++) acc2[i][j] = 0ULL;

    const int NK = (EDIM + 15) / 16;   // 19
    for (int kt = 0; kt < NK; kt++) {
        float4 av[2], bv[2];
#pragma unroll
        for (int q = 0; q < 2; q++) {
            const int kk = kt * 16 + (lqp * 2 + q) * 4;
            av[q] = make_float4(0.f, 0.f, 0.f, 0.f);
            bv[q] = make_float4(0.f, 0.f, 0.f, 0.f);
            if (kk + 3 < EDIM) {
                av[q] = *(const float4*)(W + (size_t)(ntile * 128 + lr) * EDIM + kk);   // cols
                bv[q] = *(const float4*)(Abase + (size_t)lr * EDIM + kk);               // batch
            }
        }
        __syncthreads();
#pragma unroll
        for (int q = 0; q < 2; q++) {
            const int kb = (lqp * 2 + q) * 4;
            As[kb + 0][lr] = av[q].x; As[kb + 1][lr] = av[q].y;
            As[kb + 2][lr] = av[q].z; As[kb + 3][lr] = av[q].w;
            Bs[kb + 0][lr] = bv[q].x; Bs[kb + 1][lr] = bv[q].y;
            Bs[kb + 2][lr] = bv[q].z; Bs[kb + 3][lr] = bv[q].w;
        }
        __syncthreads();
#pragma unroll
        for (int k = 0; k < 16; k++) {
            float4 aA = *(const float4*)&As[k][tm * 8];
            float4 aB = *(const float4*)&As[k][tm * 8 + 4];
            ulonglong2 bA = *(const ulonglong2*)&Bs[k][4 * tn];        // batches 4tn..4tn+3
            ulonglong2 bB = *(const ulonglong2*)&Bs[k][64 + 4 * tn];   // +64
            unsigned long long a[8];
            a[0] = pk2(aA.x, aA.x); a[1] = pk2(aA.y, aA.y);
            a[2] = pk2(aA.z, aA.z); a[3] = pk2(aA.w, aA.w);
            a[4] = pk2(aB.x, aB.x); a[5] = pk2(aB.y, aB.y);
            a[6] = pk2(aB.z, aB.z); a[7] = pk2(aB.w, aB.w);
#pragma unroll
            for (int i = 0; i < 8; i++) {
                fma2(acc2[i][0], a[i], bA.x);
                fma2(acc2[i][1], a[i], bA.y);
                fma2(acc2[i][2], a[i], bB.x);
                fma2(acc2[i][3], a[i], bB.y);
            }
        }
    }
    // epilogue: per-col bias, transposed store [s][col][b], coalesced STG.128
    float* gbase = g_gx[dir] + (size_t)s * 1024 * 128;
#pragma unroll
    for (int i = 0; i < 8; i++) {
        const int col = ntile * 128 + tm * 8 + i;
        const float bb = bi[col] + bh[col];
        float2 v0 = upk2(acc2[i][0]), v1 = upk2(acc2[i][1]);
        float2 v2 = upk2(acc2[i][2]), v3 = upk2(acc2[i][3]);
        float4 oA = make_float4(v0.x + bb, v0.y + bb, v1.x + bb, v1.y + bb);
        float4 oB = make_float4(v2.x + bb, v2.y + bb, v3.x + bb, v3.y + bb);
        *(float4*)(gbase + (size_t)col * 128 + 4 * tn)      = oA;
        *(float4*)(gbase + (size_t)col * 128 + 64 + 4 * tn) = oB;
    }
}

// ---------------- kernel 3: persistent LSTM, smem weights, 256 threads ------
// 128 CTAs x 256 threads. CTA: dir=cta&1, units u0..u0+3. Warp w: unit w>>1,
// batch-half w&1; lane owns 2 batches (natural f32x2 h pair, no duplication).
// Weights broadcast from smem dup-pairs. Tight spin barrier (no nanosleep).
__global__ __launch_bounds__(256) void lstm_persist()
{
    extern __shared__ char smraw[];
    unsigned long long (*wd)[4][4] = (unsigned long long(*)[4][4])smraw;        // [256][ui][g] dup, 32KB
    float* hs = (float*)(smraw + 256 * 16 * 8);                                  // [64][128], 32KB

    const int cta = blockIdx.x;
    const int dir = cta & 1;
    const int u0  = (cta >> 1) * 4;
    const int t   = threadIdx.x;
    const int w   = t >> 5;
    const int l   = t & 31;
    const int rg  = w >> 1;             // unit index 0..3
    const int hf  = w & 1;              // batch half
    const int u   = u0 + rg;
    const int bb  = hf * 64 + 2 * l;    // first of 2 batches

    // load weights (dup pairs) into smem
    for (int e = t; e < 256 * 16; e += 256) {
        int k = e >> 4, ui = (e >> 2) & 3, g = e & 3;
        float wv = g_Wt4[dir][k][u0 + ui][g];
        wd[k][ui][g] = pk2(wv, wv);
    }
    // zero h buf0 for this CTA's units (each (u, 2-batch) written once: rg covers u, all hf/l cover b)
    *(float2*)&g_h[dir][0][u][bb] = make_float2(0.f, 0.f);
    float c0 = 0.f, c1 = 0.f, h0v = 0.f, h1v = 0.f;
    __threadfence();
    __syncthreads();

    int epoch = 1;
    if (t == 0) {
        int v = atomicAdd(&g_bar_cnt, 1);
        if (v == epoch * NCTA_LSTM - 1) { g_bar_flag = epoch; }
        else { while (g_bar_flag < epoch) { } __threadfence(); }
    }
    __syncthreads();

    const float* gxd = g_gx[dir];

    for (int s = 0; s < S_LEN; s++) {
        const int buf = s & 1;
        const float* hsrc = &g_h[dir][buf][0][0];

        // prefetch gx for this step (4 gates x 2 batches)
        float2 gxq[4];
#pragma unroll
        for (int g = 0; g < 4; g++)
            gxq[g] = __ldcg((const float2*)(gxd + ((size_t)s * 1024 + g * 256 + u) * 128 + bb));

        unsigned long long acc[4] = {0ULL, 0ULL, 0ULL, 0ULL};

        // prefetch h chunk 0 into registers (8 float4 per thread = 32KB/CTA)
        float4 pf[8];
#pragma unroll
        for (int i = 0; i < 8; i++) pf[i] = __ldcg((const float4*)(hsrc + i * 1024 + t * 4));

        for (int cch = 0; cch < 4; cch++) {
            __syncthreads();
#pragma unroll
            for (int i = 0; i < 8; i++) *(float4*)(hs + i * 1024 + t * 4) = pf[i];
            __syncthreads();
            if (cch < 3) {
                const float* src = hsrc + (cch + 1) * 8192;
#pragma unroll
                for (int i = 0; i < 8; i++) pf[i] = __ldcg((const float4*)(src + i * 1024 + t * 4));
            }
            const int kb = cch * 64;
#pragma unroll 8
            for (int kk = 0; kk < 64; kk++) {
                unsigned long long hp = *(const unsigned long long*)(hs + kk * 128 + bb);  // (b, b+1)
                ulonglong2 wif = *(const ulonglong2*)&wd[kb + kk][rg][0];
                ulonglong2 wgo = *(const ulonglong2*)&wd[kb + kk][rg][2];
                fma2(acc[0], wif.x, hp);
                fma2(acc[1], wif.y, hp);
                fma2(acc[2], wgo.x, hp);
                fma2(acc[3], wgo.y, hp);
            }
        }
        // cell update for 2 batches
        float2 vi = upk2(acc[0]), vf = upk2(acc[1]), vg = upk2(acc[2]), vo = upk2(acc[3]);
        {
            float gi = gxq[0].x + vi.x, gf = gxq[1].x + vf.x;
            float gg = gxq[2].x + vg.x, go = gxq[3].x + vo.x;
            float cc = sigmoidf_(gf) * c0 + sigmoidf_(gi) * tanhf_(gg);
            c0 = cc; h0v = sigmoidf_(go) * tanhf_(cc);
        }
        {
            float gi = gxq[0].y + vi.y, gf = gxq[1].y + vf.y;
            float gg = gxq[2].y + vg.y, go = gxq[3].y + vo.y;
            float cc = sigmoidf_(gf) * c1 + sigmoidf_(gi) * tanhf_(gg);
            c1 = cc; h1v = sigmoidf_(go) * tanhf_(cc);
        }
        __stcg((float2*)&g_h[dir][buf ^ 1][u][bb], make_float2(h0v, h1v));
        __threadfence();
        // global barrier (tight spin, no sleep)
        epoch++;
        if (t == 0) {
            int v = atomicAdd(&g_bar_cnt, 1);
            if (v == epoch * NCTA_LSTM - 1) { g_bar_flag = epoch; }
            else { while (g_bar_flag < epoch) { } __threadfence(); }
        }
        __syncthreads();
    }
    // write final h to g_h0 [b][dir*256+u]
    g_h0[(size_t)bb * (2 * HDIM) + dir * HDIM + u]       = h0v;
    g_h0[(size_t)(bb + 1) * (2 * HDIM) + dir * HDIM + u] = h1v;
}

// ---------------- kernel 4: decoder input gates ------------------------------
__global__ __launch_bounds__(256) void dec_prep_kernel(
    const int* __restrict__ classes, const float* __restrict__ ecW,
    const float* __restrict__ dWih, const float* __restrict__ dbih)
{
    __shared__ float ce[EDIM];
    const int c = blockIdx.x;
    const int cls = classes[c];
    for (int e = threadIdx.x; e < EDIM; e += blockDim.x)
        ce[e] = tanhf_(ecW[(size_t)cls * EDIM + e]);
    __syncthreads();
    const int j = blockIdx.y * 256 + threadIdx.x;
    float acc = dbih[j];
    const float4* w = (const float4*)(dWih + (size_t)j * EDIM);
#pragma unroll 5
    for (int k = 0; k < EDIM / 4; k++) {
        float4 wv = w[k];
        acc += wv.x * ce[4 * k] + wv.y * ce[4 * k + 1] + wv.z * ce[4 * k + 2] + wv.w * ce[4 * k + 3];
    }
    g_gxc[c * 1536 + j] = acc;
}

// ---------------- kernel 5: decoder GRU + proj + cls + log_softmax ----------
__global__ __launch_bounds__(512) void dec_kernel(
    const float* __restrict__ dbhh,
    const float* __restrict__ projW, const float* __restrict__ projB,
    const float* __restrict__ clsW, const float* __restrict__ clsB,
    float* __restrict__ out)
{
    const int Gd = 2;
    const int H2 = 2 * HDIM;
    const int b0 = blockIdx.x * Gd;
    const int u  = threadIdx.x;
    const ulonglong2* W2 = (const ulonglong2*)&g_dWt4[0][0][0];

    __shared__ unsigned long long hd[2][Gd][512];
    __shared__ float hplain[Gd][512];
    __shared__ float projs[Gd][PDIM];
    __shared__ float lgs[Gd][2];

    float hprev[Gd];
#pragma unroll
    for (int b = 0; b < Gd; b++) {
        hprev[b] = g_h0[(size_t)(b0 + b) * H2 + u];
        hd[0][b][u] = pk2(hprev[b], hprev[b]);
    }
    const float bhr = dbhh[u], bhz = dbhh[H2 + u], bhn = dbhh[2 * H2 + u];
    __syncthreads();

    for (int c = 0; c < NCLS; c++) {
        const int cur = c & 1, nxt = cur ^ 1;
        unsigned long long arz[Gd], anp[Gd];
#pragma unroll
        for (int b = 0; b < Gd; b++) { arz[b] = 0ULL; anp[b] = 0ULL; }
        const unsigned long long* h0p = &hd[cur][0][0];
        const unsigned long long* h1p = &hd[cur][1][0];

#pragma unroll 4
        for (int k = 0; k < H2; k++) {
            ulonglong2 w = W2[k * H2 + u];
            unsigned long long hh0 = h0p[k], hh1 = h1p[k];
            fma2(arz[0], w.x, hh0); fma2(anp[0], w.y, hh0);
            fma2(arz[1], w.x, hh1); fma2(anp[1], w.y, hh1);
        }
        const float gxr = g_gxc[c * 1536 + u];
        const float gxz = g_gxc[c * 1536 + H2 + u];
        const float gxn = g_gxc[c * 1536 + 2 * H2 + u];
#pragma unroll
        for (int b = 0; b < Gd; b++) {
            float2 vrz = upk2(arz[b]);
            float2 vnp = upk2(anp[b]);
            float r = sigmoidf_(gxr + vrz.x + bhr);
            float z = sigmoidf_(gxz + vrz.y + bhz);
            float n = tanhf_(gxn + r * (vnp.x + bhn));
            float hn = tanhf_((1.0f - z) * n + z * hprev[b]);
            hprev[b] = hn;
            hd[nxt][b][u] = pk2(hn, hn);
            hplain[b][u] = hn;
        }
        __syncthreads();
        {
            const int b = u >> 8, p = u & 255;
            const float4* w = (const float4*)(projW + (size_t)p * H2);
            const float4* hv = (const float4*)hplain[b];
            float acc = projB[p];
            for (int k4 = 0; k4 < H2 / 4; k4++) {
                float4 wv = w[k4], hvv = hv[k4];
                acc += wv.x * hvv.x + wv.y * hvv.y + wv.z * hvv.z + wv.w * hvv.w;
            }
            projs[b][p] = acc;
        }
        __syncthreads();
        const int wid = u >> 5, lid = u & 31;
        if (wid < Gd * 2) {
            const int b = wid >> 1, cl = wid & 1;
            float acc = 0.0f;
            for (int k = lid; k < PDIM; k += 32) acc += clsW[cl * PDIM + k] * projs[b][k];
#pragma unroll
            for (int o = 16; o > 0; o >>= 1) acc += __shfl_down_sync(0xffffffffu, acc, o);
            if (lid == 0) lgs[b][cl] = acc + clsB[cl];
        }
        __syncthreads();
        if (u < Gd) {
            const int b = u;
            float l0 = lgs[b][0], l1 = lgs[b][1];
            float m = fmaxf(l0, l1);
            float lse = m + logf(expf(l0 - m) + expf(l1 - m));
            out[(size_t)c * BSZ * 2 + (b0 + b) * 2 + 0] = l0 - lse;
            out[(size_t)c * BSZ * 2 + (b0 + b) * 2 + 1] = l1 - lse;
        }
        __syncthreads();
    }
}

// ---------------- launch -----------------------------------------------------
extern "C" void kernel_launch(void* const* d_in, const int* in_sizes, int n_in,
                              void* d_out, int out_size)
{
    const int*   seq     = (const int*)d_in[0];
    const int*   classes = (const int*)d_in[1];
    const float* embW    = (const float*)d_in[2];
    const float* ecW     = (const float*)d_in[3];
    const float* fWih    = (const float*)d_in[4];
    const float* fWhh    = (const float*)d_in[5];
    const float* fbih    = (const float*)d_in[6];
    const float* fbhh    = (const float*)d_in[7];
    const float* bWih    = (const float*)d_in[8];
    const float* bWhh    = (const float*)d_in[9];
    const float* bbih    = (const float*)d_in[10];
    const float* bbhh    = (const float*)d_in[11];
    const float* dWih    = (const float*)d_in[12];
    const float* dWhh    = (const float*)d_in[13];
    const float* dbih    = (const float*)d_in[14];
    const float* dbhh    = (const float*)d_in[15];
    const float* projW   = (const float*)d_in[16];
    const float* projB   = (const float*)d_in[17];
    const float* clsW    = (const float*)d_in[18];
    const float* clsB    = (const float*)d_in[19];
    float* out = (float*)d_out;

    static int smem_set = 0;
    const int lstm_smem = 256 * 16 * 8 + 64 * 128 * 4;   // 32KB wd + 32KB hs = 64KB
    if (!smem_set) {
        cudaFuncSetAttribute(lstm_persist, cudaFuncAttributeMaxDynamicSharedMemorySize, lstm_smem);
        smem_set = 1;
    }

    {   // 0. weight transposes + barrier reset
        dim3 gl(HDIM / 32, HDIM / 32, 8);
        transpose_lstm_w<<<gl, 1024>>>(fWhh, bWhh);
        dim3 gd(2 * HDIM / 32, 2 * HDIM / 32, 3);
        transpose_dec_w<<<gd, 1024>>>(dWhh);
    }
    {   // 1. embeddings
        long long total = (long long)S_LEN * BSZ * EDIM;
        int blocks = (int)((total + 255) / 256);
        embed_kernel<<<blocks, 256>>>(seq, embW);
    }
    {   // 2. input-gate GEMMs, transposed output
        dim3 grid(S_LEN, 1024 / 128, 2);
        gx_gemm_kernel<<<grid, 256>>>(fWih, fbih, fbhh, bWih, bbih, bbhh);
    }
    {   // 3. persistent bidirectional LSTM (256 threads/CTA)
        lstm_persist<<<NCTA_LSTM, 256, lstm_smem>>>();
    }
    {   // 4. decoder input gates per class
        dim3 grid(NCLS, 6);
        dec_prep_kernel<<<grid, 256>>>(classes, ecW, dWih, dbih);
    }
    {   // 5. decoder GRU + projection + classifier + log_softmax
        dec_kernel<<<BSZ / 2, 512>>>(dbhh, projW, projB, clsW, clsB, out);
    }
    (void)in_sizes; (void)n_in; (void)out_size;
}